// round 6
// baseline (speedup 1.0000x reference)
#include <cuda_runtime.h>

#define SEQ    4096
#define HID    512
#define G4     2048          // 4*HID
#define NCD    64            // CTAs per direction in the recurrence
#define JH     8             // h outputs per CTA (32 gate rows)

// ---------------- scratch (device globals; no allocation allowed) ----------------
static __device__ __align__(16) float    g_x0 [SEQ * HID];        // embedded input
static __device__ __align__(16) float    g_xpf[SEQ * G4];         // xproj forward
static __device__ __align__(16) float    g_xpb[SEQ * G4];         // xproj backward
static __device__ __align__(16) float    g_h0 [SEQ * 2 * HID];    // layer0 output
static __device__ __align__(16) float    g_h1 [SEQ * 2 * HID];    // layer1 output
static __device__ __align__(16) float    g_hbuf[2][2 * HID];      // [dir][parity*HID] hidden state
static __device__                unsigned g_bar[2];               // per-direction step counters

// ---------------- embed ----------------
__global__ void embed_kernel(const int* __restrict__ idx, const float* __restrict__ ew) {
    int s = blockIdx.x;               // 4096 blocks, 128 threads
    int r = idx[s];
    ((float4*)(g_x0 + (size_t)s * HID))[threadIdx.x] =
        ((const float4*)(ew + (size_t)r * HID))[threadIdx.x];
}

__global__ void reset_kernel() {
    if (threadIdx.x < 2) g_bar[threadIdx.x] = 0u;
}

// ---------------- fp32 GEMM:  C[M][N] = A[M][K] * B[N][K]^T + bias[N] ----------------
// Tiles: BM=128, BN=256, BK=8; 256 threads; 8x16 microtile; packed f32x2 FMA.
__device__ __forceinline__ unsigned long long dupf(float a) {
    unsigned long long r;
    unsigned ai = __float_as_uint(a);
    asm("mov.b64 %0, {%1, %2};" : "=l"(r) : "r"(ai), "r"(ai));
    return r;
}
#define FFMA2(acc_, a_, b_) asm("fma.rn.f32x2 %0, %1, %2, %0;" : "+l"(acc_) : "l"(a_), "l"(b_))

__device__ __forceinline__ unsigned ldcg_u32(const unsigned* p) {
    unsigned v;
    asm volatile("ld.global.cg.u32 %0, [%1];" : "=r"(v) : "l"(p) : "memory");
    return v;
}

__global__ void __launch_bounds__(256, 1) gemm_nt_bias(
    const float* __restrict__ A,     // [M][K]
    const float* __restrict__ B,     // [N][K]
    const float* __restrict__ bias,  // [N]
    float* __restrict__ C,           // [M][N]
    int M, int N, int K)
{
    __shared__ __align__(16) float As[2][8][128];
    __shared__ __align__(16) float Bs[2][8][256];

    const int tid = threadIdx.x;
    const int bm  = blockIdx.y * 128;
    const int bn  = blockIdx.x * 256;
    const int tx  = tid & 15;         // 16 col-groups of 16
    const int ty  = tid >> 4;         // 16 row-groups of 8

    const int arow = tid >> 1;                 // 0..127
    const int akc  = (tid & 1) * 4;            // 0 or 4
    const float* Ap = A + (size_t)(bm + arow) * K + akc;
    const float* Bp = B + (size_t)(bn + tid) * K;

    float4 aR  = __ldg((const float4*)Ap);
    float4 bR0 = __ldg((const float4*)Bp);
    float4 bR1 = __ldg((const float4*)(Bp + 4));

    unsigned long long acc[8][8];
#pragma unroll
    for (int i = 0; i < 8; i++)
#pragma unroll
        for (int j = 0; j < 8; j++) acc[i][j] = 0ull;

    const int nk = K >> 3;
    for (int kt = 0; kt < nk; kt++) {
        const int buf = kt & 1;
        As[buf][akc + 0][arow] = aR.x;
        As[buf][akc + 1][arow] = aR.y;
        As[buf][akc + 2][arow] = aR.z;
        As[buf][akc + 3][arow] = aR.w;
        Bs[buf][0][tid] = bR0.x;  Bs[buf][1][tid] = bR0.y;
        Bs[buf][2][tid] = bR0.z;  Bs[buf][3][tid] = bR0.w;
        Bs[buf][4][tid] = bR1.x;  Bs[buf][5][tid] = bR1.y;
        Bs[buf][6][tid] = bR1.z;  Bs[buf][7][tid] = bR1.w;
        __syncthreads();
        if (kt + 1 < nk) {
            aR  = __ldg((const float4*)(Ap + (size_t)(kt + 1) * 8));
            bR0 = __ldg((const float4*)(Bp + (size_t)(kt + 1) * 8));
            bR1 = __ldg((const float4*)(Bp + (size_t)(kt + 1) * 8 + 4));
        }
#pragma unroll
        for (int k = 0; k < 8; k++) {
            const float* ak = &As[buf][k][ty * 8];
            float4 a0 = *(const float4*)ak;
            float4 a1 = *(const float4*)(ak + 4);
            const double2* bk = (const double2*)&Bs[buf][k][tx * 16];
            double2 q0 = bk[0], q1 = bk[1], q2 = bk[2], q3 = bk[3];
            unsigned long long bb[8];
            bb[0] = __double_as_longlong(q0.x);  bb[1] = __double_as_longlong(q0.y);
            bb[2] = __double_as_longlong(q1.x);  bb[3] = __double_as_longlong(q1.y);
            bb[4] = __double_as_longlong(q2.x);  bb[5] = __double_as_longlong(q2.y);
            bb[6] = __double_as_longlong(q3.x);  bb[7] = __double_as_longlong(q3.y);
            float av[8] = {a0.x, a0.y, a0.z, a0.w, a1.x, a1.y, a1.z, a1.w};
#pragma unroll
            for (int i = 0; i < 8; i++) {
                unsigned long long ad = dupf(av[i]);
#pragma unroll
                for (int j = 0; j < 8; j++) FFMA2(acc[i][j], ad, bb[j]);
            }
        }
    }

    float bias16[16];
#pragma unroll
    for (int q = 0; q < 4; q++)
        *(float4*)&bias16[q * 4] = __ldg((const float4*)&bias[bn + tx * 16 + q * 4]);
#pragma unroll
    for (int i = 0; i < 8; i++) {
        float outv[16];
#pragma unroll
        for (int j = 0; j < 8; j++) {
            union { unsigned long long u; float2 f; } cv;
            cv.u = acc[i][j];
            outv[2 * j]     = cv.f.x + bias16[2 * j];
            outv[2 * j + 1] = cv.f.y + bias16[2 * j + 1];
        }
        float* crow = C + (size_t)(bm + ty * 8 + i) * N + bn + tx * 16;
#pragma unroll
        for (int q = 0; q < 4; q++) *(float4*)&crow[q * 4] = *(float4*)&outv[q * 4];
    }
}

// ---------------- persistent bidirectional LSTM layer ----------------
// R5 kernel with three deltas:
//  1) gated strong-confirm spin (exit condition identical to R1: strong RMW >= target)
//  2) xproj prefetch hoisted above the barrier (immutable data)
//  3) __expf-based gates
__global__ void __launch_bounds__(256, 1) lstm_layer_kernel(
    const float* __restrict__ xpf, const float* __restrict__ xpb,
    const float* __restrict__ Whf, const float* __restrict__ Whb,
    float* __restrict__ hcat)
{
    __shared__ __align__(16) float hsh[HID];
    __shared__ float xps[32];
    __shared__ float pre[32];
    __shared__ float csh[JH];

    const int tid = threadIdx.x;
    const int dir = blockIdx.x >> 6;       // NCD == 64
    const int cid = blockIdx.x & 63;
    const float* xp = dir ? xpb : xpf;
    const float* W  = dir ? Whb : Whf;
    unsigned* bar = &g_bar[dir];
    float* hbuf = g_hbuf[dir];

    const int rp   = tid >> 4;             // 16 row-pairs
    const int ks   = tid & 15;             // 16 k-slices (strided by 4 floats)
    const int row0 = rp * 2, row1 = rp * 2 + 1;

    // ---- this thread's Whh values, scalar registers (proven in R5) ----
    float w0r[32], w1r[32];
    {
        const int g0 = row0 >> 3, j0 = row0 & 7;
        const int g1 = row1 >> 3, j1 = row1 & 7;
        const size_t gr0 = (size_t)(g0 * HID + cid * JH + j0) * HID;
        const size_t gr1 = (size_t)(g1 * HID + cid * JH + j1) * HID;
#pragma unroll
        for (int m = 0; m < 8; m++) {
            const int k = ks * 4 + m * 64;
            float4 v0 = __ldg((const float4*)&W[gr0 + k]);
            float4 v1 = __ldg((const float4*)&W[gr1 + k]);
            w0r[4 * m + 0] = v0.x;  w0r[4 * m + 1] = v0.y;
            w0r[4 * m + 2] = v0.z;  w0r[4 * m + 3] = v0.w;
            w1r[4 * m + 0] = v1.x;  w1r[4 * m + 1] = v1.y;
            w1r[4 * m + 2] = v1.z;  w1r[4 * m + 3] = v1.w;
        }
    }
    if (tid < 128) ((float4*)hsh)[tid] = make_float4(0.f, 0.f, 0.f, 0.f);
    if (tid < JH) csh[tid] = 0.f;
    __syncthreads();

    for (int t = 0; t < SEQ; t++) {
        const int tt = dir ? (SEQ - 1 - t) : t;
        // prefetch this step's xproj values (immutable; hides latency behind spin)
        float xval = 0.f;
        if (tid < 32) {
            int g = tid >> 3, j = tid & 7;
            xval = __ldg(&xp[(size_t)tt * G4 + g * HID + cid * JH + j]);
        }
        if (t > 0) {
            if (tid == 0) {
                const unsigned target = (unsigned)NCD * (unsigned)t;
                unsigned v;
                do {
                    while (ldcg_u32(bar) < target) { }   // cheap weak watch
                    v = atomicAdd(bar, 0u);              // strong RMW; exit iff >= target
                } while (v < target);
                __threadfence();           // acquire
            }
            __syncthreads();
            if (tid < 128) {
                const float4* hp = (const float4*)&hbuf[((t - 1) & 1) * HID];
                ((float4*)hsh)[tid] = __ldcg(hp + tid);   // L2 (bypass stale L1)
            }
            __syncthreads();
        }
        // matvec: pre[r] = sum_k h[k] * Whh[r][k], 2 rows per thread, strided k
        float a0 = 0.f, a1 = 0.f;
#pragma unroll
        for (int m = 0; m < 8; m++) {
            int k = ks * 4 + m * 64;
            float4 h4 = *(const float4*)&hsh[k];
            a0 += h4.x * w0r[4 * m] + h4.y * w0r[4 * m + 1]
                + h4.z * w0r[4 * m + 2] + h4.w * w0r[4 * m + 3];
            a1 += h4.x * w1r[4 * m] + h4.y * w1r[4 * m + 1]
                + h4.z * w1r[4 * m + 2] + h4.w * w1r[4 * m + 3];
        }
#pragma unroll
        for (int off = 8; off > 0; off >>= 1) {
            a0 += __shfl_down_sync(0xffffffffu, a0, off, 16);
            a1 += __shfl_down_sync(0xffffffffu, a1, off, 16);
        }
        if (ks == 0) { pre[row0] = a0; pre[row1] = a1; }
        if (tid < 32) xps[tid] = xval;
        __syncthreads();

        if (tid < JH) {
            const int j = tid;
            float zi = xps[j]      + pre[j];
            float zf = xps[8 + j]  + pre[8 + j];
            float zg = xps[16 + j] + pre[16 + j];
            float zo = xps[24 + j] + pre[24 + j];
            float ig = 1.f / (1.f + __expf(-zi));
            float fg = 1.f / (1.f + __expf(-zf));
            float gg = 2.f / (1.f + __expf(-2.f * zg)) - 1.f;
            float og = 1.f / (1.f + __expf(-zo));
            float c  = fg * csh[j] + ig * gg;
            csh[j] = c;
            float tc = 2.f / (1.f + __expf(-2.f * c)) - 1.f;
            float h  = og * tc;
            const int hj = cid * JH + j;
            __stcg(&hbuf[(t & 1) * HID + hj], h);                     // broadcast state
            hcat[(size_t)tt * (2 * HID) + dir * HID + hj] = h;        // layer output
            __threadfence();                                          // release stores
        }
        __syncthreads();
        if (tid == 0) atomicAdd(bar, 1u);
    }
}

// ---------------- launch ----------------
extern "C" void kernel_launch(void* const* d_in, const int* in_sizes, int n_in,
                              void* d_out, int out_size)
{
    (void)in_sizes; (void)n_in; (void)out_size;
    const int*   idx   = (const int*)  d_in[0];
    const float* ew    = (const float*)d_in[1];
    const float* Wih0f = (const float*)d_in[2];
    const float* Whh0f = (const float*)d_in[3];
    const float* b0f   = (const float*)d_in[4];
    const float* Wih0b = (const float*)d_in[5];
    const float* Whh0b = (const float*)d_in[6];
    const float* b0b   = (const float*)d_in[7];
    const float* Wih1f = (const float*)d_in[8];
    const float* Whh1f = (const float*)d_in[9];
    const float* b1f   = (const float*)d_in[10];
    const float* Wih1b = (const float*)d_in[11];
    const float* Whh1b = (const float*)d_in[12];
    const float* b1b   = (const float*)d_in[13];
    const float* Wlin  = (const float*)d_in[14];
    const float* blin  = (const float*)d_in[15];
    float* out = (float*)d_out;

    float *x0, *xpf, *xpb, *h0, *h1;
    cudaGetSymbolAddress((void**)&x0,  g_x0);
    cudaGetSymbolAddress((void**)&xpf, g_xpf);
    cudaGetSymbolAddress((void**)&xpb, g_xpb);
    cudaGetSymbolAddress((void**)&h0,  g_h0);
    cudaGetSymbolAddress((void**)&h1,  g_h1);

    // 1) embed
    embed_kernel<<<SEQ, 128>>>(idx, ew);

    // 2) layer-0 input projections (K=512, N=2048)
    {
        dim3 grid(G4 / 256, SEQ / 128);
        gemm_nt_bias<<<grid, 256>>>(x0, Wih0f, b0f, xpf, SEQ, G4, HID);
        gemm_nt_bias<<<grid, 256>>>(x0, Wih0b, b0b, xpb, SEQ, G4, HID);
    }
    // 3) layer-0 recurrence
    reset_kernel<<<1, 32>>>();
    lstm_layer_kernel<<<2 * NCD, 256>>>(xpf, xpb, Whh0f, Whh0b, h0);

    // 4) layer-1 input projections (K=1024, N=2048) — reuse xp buffers
    {
        dim3 grid(G4 / 256, SEQ / 128);
        gemm_nt_bias<<<grid, 256>>>(h0, Wih1f, b1f, xpf, SEQ, G4, 2 * HID);
        gemm_nt_bias<<<grid, 256>>>(h0, Wih1b, b1b, xpb, SEQ, G4, 2 * HID);
    }
    // 5) layer-1 recurrence
    reset_kernel<<<1, 32>>>();
    lstm_layer_kernel<<<2 * NCD, 256>>>(xpf, xpb, Whh1f, Whh1b, h1);

    // 6) output head: [4096,1024] x [32000,1024]^T + blin
    {
        dim3 grid(32000 / 256, SEQ / 128);
        gemm_nt_bias<<<grid, 256>>>(h1, Wlin, blin, out, SEQ, 32000, 2 * HID);
    }
}

// round 7
// speedup vs baseline: 1.0418x; 1.0418x over previous
#include <cuda_runtime.h>

#define SEQ    4096
#define HID    512
#define G4     2048          // 4*HID
#define NCD    32            // CTAs per direction in the recurrence
#define NTH    512           // threads per LSTM CTA
#define JH     16            // h outputs per CTA (64 gate rows)

// ---------------- scratch (device globals; no allocation allowed) ----------------
static __device__ __align__(16) float    g_x0 [SEQ * HID];        // embedded input
static __device__ __align__(16) float    g_xpf[SEQ * G4];         // xproj forward
static __device__ __align__(16) float    g_xpb[SEQ * G4];         // xproj backward
static __device__ __align__(16) float    g_h0 [SEQ * 2 * HID];    // layer0 output
static __device__ __align__(16) float    g_h1 [SEQ * 2 * HID];    // layer1 output
static __device__ __align__(16) float    g_hbuf[2][2 * HID];      // [dir][parity*HID] hidden state
static __device__ __align__(16) unsigned g_bar[4];                // [layer][dir] step counters

// ---------------- embed (+ counter reset for both LSTM layers) ----------------
__global__ void embed_kernel(const int* __restrict__ idx, const float* __restrict__ ew) {
    if (blockIdx.x == 0 && threadIdx.x < 4) g_bar[threadIdx.x] = 0u;
    int s = blockIdx.x;               // 4096 blocks, 128 threads
    int r = idx[s];
    ((float4*)(g_x0 + (size_t)s * HID))[threadIdx.x] =
        ((const float4*)(ew + (size_t)r * HID))[threadIdx.x];
}

// ---------------- fp32 GEMM:  C[M][N] = A[M][K] * B[N][K]^T + bias[N] ----------------
// Tiles: BM=128, BN=256, BK=8; 256 threads; 8x16 microtile; packed f32x2 FMA.
__device__ __forceinline__ unsigned long long dupf(float a) {
    unsigned long long r;
    unsigned ai = __float_as_uint(a);
    asm("mov.b64 %0, {%1, %2};" : "=l"(r) : "r"(ai), "r"(ai));
    return r;
}
#define FFMA2(acc_, a_, b_) asm("fma.rn.f32x2 %0, %1, %2, %0;" : "+l"(acc_) : "l"(a_), "l"(b_))

__global__ void __launch_bounds__(256, 1) gemm_nt_bias(
    const float* __restrict__ A,     // [M][K]
    const float* __restrict__ B,     // [N][K]
    const float* __restrict__ bias,  // [N]
    float* __restrict__ C,           // [M][N]
    int M, int N, int K)
{
    __shared__ __align__(16) float As[2][8][128];
    __shared__ __align__(16) float Bs[2][8][256];

    const int tid = threadIdx.x;
    const int bm  = blockIdx.y * 128;
    const int bn  = blockIdx.x * 256;
    const int tx  = tid & 15;         // 16 col-groups of 16
    const int ty  = tid >> 4;         // 16 row-groups of 8

    const int arow = tid >> 1;                 // 0..127
    const int akc  = (tid & 1) * 4;            // 0 or 4
    const float* Ap = A + (size_t)(bm + arow) * K + akc;
    const float* Bp = B + (size_t)(bn + tid) * K;

    float4 aR  = __ldg((const float4*)Ap);
    float4 bR0 = __ldg((const float4*)Bp);
    float4 bR1 = __ldg((const float4*)(Bp + 4));

    unsigned long long acc[8][8];
#pragma unroll
    for (int i = 0; i < 8; i++)
#pragma unroll
        for (int j = 0; j < 8; j++) acc[i][j] = 0ull;

    const int nk = K >> 3;
    for (int kt = 0; kt < nk; kt++) {
        const int buf = kt & 1;
        As[buf][akc + 0][arow] = aR.x;
        As[buf][akc + 1][arow] = aR.y;
        As[buf][akc + 2][arow] = aR.z;
        As[buf][akc + 3][arow] = aR.w;
        Bs[buf][0][tid] = bR0.x;  Bs[buf][1][tid] = bR0.y;
        Bs[buf][2][tid] = bR0.z;  Bs[buf][3][tid] = bR0.w;
        Bs[buf][4][tid] = bR1.x;  Bs[buf][5][tid] = bR1.y;
        Bs[buf][6][tid] = bR1.z;  Bs[buf][7][tid] = bR1.w;
        __syncthreads();
        if (kt + 1 < nk) {
            aR  = __ldg((const float4*)(Ap + (size_t)(kt + 1) * 8));
            bR0 = __ldg((const float4*)(Bp + (size_t)(kt + 1) * 8));
            bR1 = __ldg((const float4*)(Bp + (size_t)(kt + 1) * 8 + 4));
        }
#pragma unroll
        for (int k = 0; k < 8; k++) {
            const float* ak = &As[buf][k][ty * 8];
            float4 a0 = *(const float4*)ak;
            float4 a1 = *(const float4*)(ak + 4);
            const double2* bk = (const double2*)&Bs[buf][k][tx * 16];
            double2 q0 = bk[0], q1 = bk[1], q2 = bk[2], q3 = bk[3];
            unsigned long long bb[8];
            bb[0] = __double_as_longlong(q0.x);  bb[1] = __double_as_longlong(q0.y);
            bb[2] = __double_as_longlong(q1.x);  bb[3] = __double_as_longlong(q1.y);
            bb[4] = __double_as_longlong(q2.x);  bb[5] = __double_as_longlong(q2.y);
            bb[6] = __double_as_longlong(q3.x);  bb[7] = __double_as_longlong(q3.y);
            float av[8] = {a0.x, a0.y, a0.z, a0.w, a1.x, a1.y, a1.z, a1.w};
#pragma unroll
            for (int i = 0; i < 8; i++) {
                unsigned long long ad = dupf(av[i]);
#pragma unroll
                for (int j = 0; j < 8; j++) FFMA2(acc[i][j], ad, bb[j]);
            }
        }
    }

    float bias16[16];
#pragma unroll
    for (int q = 0; q < 4; q++)
        *(float4*)&bias16[q * 4] = __ldg((const float4*)&bias[bn + tx * 16 + q * 4]);
#pragma unroll
    for (int i = 0; i < 8; i++) {
        float outv[16];
#pragma unroll
        for (int j = 0; j < 8; j++) {
            union { unsigned long long u; float2 f; } cv;
            cv.u = acc[i][j];
            outv[2 * j]     = cv.f.x + bias16[2 * j];
            outv[2 * j + 1] = cv.f.y + bias16[2 * j + 1];
        }
        float* crow = C + (size_t)(bm + ty * 8 + i) * N + bn + tx * 16;
#pragma unroll
        for (int q = 0; q < 4; q++) *(float4*)&crow[q * 4] = *(float4*)&outv[q * 4];
    }
}

// ---------------- persistent bidirectional LSTM layer ----------------
// NCD=32 CTAs/dir x 512 threads; each CTA owns JH=16 h-outputs (64 gate rows).
// Whh slice in scalar registers (64/thread, proven R5). R1's exact atomic
// counter protocol (proven). __expf gates (proven R6). xproj prefetch (proven R6).
__global__ void __launch_bounds__(NTH, 1) lstm_layer_kernel(
    const float* __restrict__ xpf, const float* __restrict__ xpb,
    const float* __restrict__ Whf, const float* __restrict__ Whb,
    float* __restrict__ hcat, unsigned* __restrict__ barbase)
{
    __shared__ __align__(16) float hsh[HID];
    __shared__ float xps[4 * JH];          // 64
    __shared__ float pre[4 * JH];          // 64
    __shared__ float csh[JH];              // 16

    const int tid = threadIdx.x;
    const int dir = blockIdx.x >> 5;       // NCD == 32
    const int cid = blockIdx.x & 31;
    const float* xp = dir ? xpb : xpf;
    const float* W  = dir ? Whb : Whf;
    unsigned* bar = barbase + dir;
    float* hbuf = g_hbuf[dir];

    const int rp   = tid >> 4;             // 32 row-pairs (0..31)
    const int ks   = tid & 15;             // 16 k-slices (strided by 4 floats)
    const int row0 = rp * 2, row1 = rp * 2 + 1;   // local rows 0..63

    // ---- this thread's Whh values, scalar registers ----
    // local row rl = g*JH + j  <->  global row g*HID + cid*JH + j
    float w0r[32], w1r[32];
    {
        const int g0 = row0 >> 4, j0 = row0 & 15;
        const int g1 = row1 >> 4, j1 = row1 & 15;
        const size_t gr0 = (size_t)(g0 * HID + cid * JH + j0) * HID;
        const size_t gr1 = (size_t)(g1 * HID + cid * JH + j1) * HID;
#pragma unroll
        for (int m = 0; m < 8; m++) {
            const int k = ks * 4 + m * 64;
            float4 v0 = __ldg((const float4*)&W[gr0 + k]);
            float4 v1 = __ldg((const float4*)&W[gr1 + k]);
            w0r[4 * m + 0] = v0.x;  w0r[4 * m + 1] = v0.y;
            w0r[4 * m + 2] = v0.z;  w0r[4 * m + 3] = v0.w;
            w1r[4 * m + 0] = v1.x;  w1r[4 * m + 1] = v1.y;
            w1r[4 * m + 2] = v1.z;  w1r[4 * m + 3] = v1.w;
        }
    }
    if (tid < 128) ((float4*)hsh)[tid] = make_float4(0.f, 0.f, 0.f, 0.f);
    if (tid < JH) csh[tid] = 0.f;
    __syncthreads();

    for (int t = 0; t < SEQ; t++) {
        const int tt = dir ? (SEQ - 1 - t) : t;
        // prefetch this step's xproj values (immutable; includes bias)
        float xval = 0.f;
        if (tid < 4 * JH) {
            int g = tid >> 4, j = tid & 15;
            xval = __ldg(&xp[(size_t)tt * G4 + g * HID + cid * JH + j]);
        }
        if (t > 0) {
            if (tid == 0) {
                const unsigned target = (unsigned)NCD * (unsigned)t;
                while (atomicAdd(bar, 0u) < target) { }
                __threadfence();           // acquire
            }
            __syncthreads();
            if (tid < 128) {
                const float4* hp = (const float4*)&hbuf[((t - 1) & 1) * HID];
                ((float4*)hsh)[tid] = __ldcg(hp + tid);   // L2 (bypass stale L1)
            }
            __syncthreads();
        }
        // matvec: pre[r] = sum_k h[k] * Whh[r][k], 2 rows per thread, strided k
        float a0 = 0.f, a1 = 0.f;
#pragma unroll
        for (int m = 0; m < 8; m++) {
            int k = ks * 4 + m * 64;
            float4 h4 = *(const float4*)&hsh[k];
            a0 += h4.x * w0r[4 * m] + h4.y * w0r[4 * m + 1]
                + h4.z * w0r[4 * m + 2] + h4.w * w0r[4 * m + 3];
            a1 += h4.x * w1r[4 * m] + h4.y * w1r[4 * m + 1]
                + h4.z * w1r[4 * m + 2] + h4.w * w1r[4 * m + 3];
        }
#pragma unroll
        for (int off = 8; off > 0; off >>= 1) {
            a0 += __shfl_down_sync(0xffffffffu, a0, off, 16);
            a1 += __shfl_down_sync(0xffffffffu, a1, off, 16);
        }
        if (ks == 0) { pre[row0] = a0; pre[row1] = a1; }
        if (tid < 4 * JH) xps[tid] = xval;
        __syncthreads();

        if (tid < JH) {
            const int j = tid;
            float zi = xps[j]           + pre[j];
            float zf = xps[JH + j]      + pre[JH + j];
            float zg = xps[2 * JH + j]  + pre[2 * JH + j];
            float zo = xps[3 * JH + j]  + pre[3 * JH + j];
            float ig = 1.f / (1.f + __expf(-zi));
            float fg = 1.f / (1.f + __expf(-zf));
            float gg = 2.f / (1.f + __expf(-2.f * zg)) - 1.f;
            float og = 1.f / (1.f + __expf(-zo));
            float c  = fg * csh[j] + ig * gg;
            csh[j] = c;
            float tc = 2.f / (1.f + __expf(-2.f * c)) - 1.f;
            float h  = og * tc;
            const int hj = cid * JH + j;
            __stcg(&hbuf[(t & 1) * HID + hj], h);                     // broadcast state
            hcat[(size_t)tt * (2 * HID) + dir * HID + hj] = h;        // layer output
            __threadfence();                                          // release stores
        }
        __syncthreads();
        if (tid == 0) atomicAdd(bar, 1u);
    }
}

// ---------------- launch ----------------
extern "C" void kernel_launch(void* const* d_in, const int* in_sizes, int n_in,
                              void* d_out, int out_size)
{
    (void)in_sizes; (void)n_in; (void)out_size;
    const int*   idx   = (const int*)  d_in[0];
    const float* ew    = (const float*)d_in[1];
    const float* Wih0f = (const float*)d_in[2];
    const float* Whh0f = (const float*)d_in[3];
    const float* b0f   = (const float*)d_in[4];
    const float* Wih0b = (const float*)d_in[5];
    const float* Whh0b = (const float*)d_in[6];
    const float* b0b   = (const float*)d_in[7];
    const float* Wih1f = (const float*)d_in[8];
    const float* Whh1f = (const float*)d_in[9];
    const float* b1f   = (const float*)d_in[10];
    const float* Wih1b = (const float*)d_in[11];
    const float* Whh1b = (const float*)d_in[12];
    const float* b1b   = (const float*)d_in[13];
    const float* Wlin  = (const float*)d_in[14];
    const float* blin  = (const float*)d_in[15];
    float* out = (float*)d_out;

    float *x0, *xpf, *xpb, *h0, *h1; unsigned* bars;
    cudaGetSymbolAddress((void**)&x0,  g_x0);
    cudaGetSymbolAddress((void**)&xpf, g_xpf);
    cudaGetSymbolAddress((void**)&xpb, g_xpb);
    cudaGetSymbolAddress((void**)&h0,  g_h0);
    cudaGetSymbolAddress((void**)&h1,  g_h1);
    cudaGetSymbolAddress((void**)&bars, g_bar);

    // 0) embed + counter reset (launch #0)
    embed_kernel<<<SEQ, 128>>>(idx, ew);

    // 1,2) layer-0 input projections (K=512)
    {
        dim3 grid(G4 / 256, SEQ / 128);
        gemm_nt_bias<<<grid, 256>>>(x0, Wih0f, b0f, xpf, SEQ, G4, HID);
        gemm_nt_bias<<<grid, 256>>>(x0, Wih0b, b0b, xpb, SEQ, G4, HID);
    }
    // 3) layer-0 recurrence (launch #3 — lands under ncu's capture window)
    lstm_layer_kernel<<<2 * NCD, NTH>>>(xpf, xpb, Whh0f, Whh0b, h0, bars);

    // 4,5) layer-1 input projections (K=1024)
    {
        dim3 grid(G4 / 256, SEQ / 128);
        gemm_nt_bias<<<grid, 256>>>(h0, Wih1f, b1f, xpf, SEQ, G4, 2 * HID);
        gemm_nt_bias<<<grid, 256>>>(h0, Wih1b, b1b, xpb, SEQ, G4, 2 * HID);
    }
    // 6) layer-1 recurrence
    lstm_layer_kernel<<<2 * NCD, NTH>>>(xpf, xpb, Whh1f, Whh1b, h1, bars + 2);

    // 7) output head: [4096,1024] x [32000,1024]^T + blin
    {
        dim3 grid(32000 / 256, SEQ / 128);
        gemm_nt_bias<<<grid, 256>>>(h1, Wlin, blin, out, SEQ, 32000, 2 * HID);
    }
}

// round 9
// speedup vs baseline: 1.3020x; 1.2497x over previous
#include <cuda_runtime.h>
#include <cuda_bf16.h>
#include <cstdint>

#define SEQ    4096
#define HID    512
#define G4     2048          // 4*HID
#define NCD    32            // CTAs per direction in the recurrence
#define NTH    512           // threads per LSTM CTA
#define JH     16            // h outputs per CTA (64 gate rows)
#define VOC    32000
#define KH     1024          // head GEMM K (2*HID)

// ---------------- scratch (device globals; no allocation allowed) ----------------
static __device__ __align__(16) float    g_x0 [SEQ * HID];
static __device__ __align__(16) float    g_xpf[SEQ * G4];
static __device__ __align__(16) float    g_xpb[SEQ * G4];
static __device__ __align__(16) float    g_h0 [SEQ * 2 * HID];
static __device__ __align__(16) float    g_h1 [SEQ * 2 * HID];
static __device__ __align__(16) float    g_hbuf[2][2 * HID];
static __device__ __align__(16) unsigned g_bar[4];
// bf16 hi/lo splits for the tensor-core head GEMM
static __device__ __align__(16) __nv_bfloat16 g_whi[VOC * KH];
static __device__ __align__(16) __nv_bfloat16 g_wlo[VOC * KH];
static __device__ __align__(16) __nv_bfloat16 g_ahi[SEQ * KH];
static __device__ __align__(16) __nv_bfloat16 g_alo[SEQ * KH];

// ---------------- embed (+ counter reset) ----------------
__global__ void embed_kernel(const int* __restrict__ idx, const float* __restrict__ ew) {
    if (blockIdx.x == 0 && threadIdx.x < 4) g_bar[threadIdx.x] = 0u;
    int s = blockIdx.x;
    int r = idx[s];
    ((float4*)(g_x0 + (size_t)s * HID))[threadIdx.x] =
        ((const float4*)(ew + (size_t)r * HID))[threadIdx.x];
}

// ---------------- fp32 -> bf16 hi/lo split ----------------
__global__ void split_bf16(const float* __restrict__ src,
                           __nv_bfloat16* __restrict__ hi, __nv_bfloat16* __restrict__ lo) {
    int i = blockIdx.x * 256 + threadIdx.x;        // one float4 per thread
    float4 v = __ldg((const float4*)src + i);
    __nv_bfloat16 h0 = __float2bfloat16_rn(v.x), h1 = __float2bfloat16_rn(v.y);
    __nv_bfloat16 h2 = __float2bfloat16_rn(v.z), h3 = __float2bfloat16_rn(v.w);
    __nv_bfloat16 l0 = __float2bfloat16_rn(v.x - __bfloat162float(h0));
    __nv_bfloat16 l1 = __float2bfloat16_rn(v.y - __bfloat162float(h1));
    __nv_bfloat16 l2 = __float2bfloat16_rn(v.z - __bfloat162float(h2));
    __nv_bfloat16 l3 = __float2bfloat16_rn(v.w - __bfloat162float(h3));
    ushort4 hv = make_ushort4(*(unsigned short*)&h0, *(unsigned short*)&h1,
                              *(unsigned short*)&h2, *(unsigned short*)&h3);
    ushort4 lv = make_ushort4(*(unsigned short*)&l0, *(unsigned short*)&l1,
                              *(unsigned short*)&l2, *(unsigned short*)&l3);
    ((ushort4*)hi)[i] = hv;
    ((ushort4*)lo)[i] = lv;
}

// ---------------- fp32 GEMM (xproj only):  C = A * B^T + bias ----------------
__device__ __forceinline__ unsigned long long dupf(float a) {
    unsigned long long r; unsigned ai = __float_as_uint(a);
    asm("mov.b64 %0, {%1, %2};" : "=l"(r) : "r"(ai), "r"(ai));
    return r;
}
#define FFMA2(acc_, a_, b_) asm("fma.rn.f32x2 %0, %1, %2, %0;" : "+l"(acc_) : "l"(a_), "l"(b_))

__global__ void __launch_bounds__(256, 1) gemm_nt_bias(
    const float* __restrict__ A, const float* __restrict__ B,
    const float* __restrict__ bias, float* __restrict__ C,
    int M, int N, int K)
{
    __shared__ __align__(16) float As[2][8][128];
    __shared__ __align__(16) float Bs[2][8][256];
    const int tid = threadIdx.x;
    const int bm  = blockIdx.y * 128;
    const int bn  = blockIdx.x * 256;
    const int tx  = tid & 15;
    const int ty  = tid >> 4;
    const int arow = tid >> 1;
    const int akc  = (tid & 1) * 4;
    const float* Ap = A + (size_t)(bm + arow) * K + akc;
    const float* Bp = B + (size_t)(bn + tid) * K;

    float4 aR  = __ldg((const float4*)Ap);
    float4 bR0 = __ldg((const float4*)Bp);
    float4 bR1 = __ldg((const float4*)(Bp + 4));

    unsigned long long acc[8][8];
#pragma unroll
    for (int i = 0; i < 8; i++)
#pragma unroll
        for (int j = 0; j < 8; j++) acc[i][j] = 0ull;

    const int nk = K >> 3;
    for (int kt = 0; kt < nk; kt++) {
        const int buf = kt & 1;
        As[buf][akc + 0][arow] = aR.x;  As[buf][akc + 1][arow] = aR.y;
        As[buf][akc + 2][arow] = aR.z;  As[buf][akc + 3][arow] = aR.w;
        Bs[buf][0][tid] = bR0.x;  Bs[buf][1][tid] = bR0.y;
        Bs[buf][2][tid] = bR0.z;  Bs[buf][3][tid] = bR0.w;
        Bs[buf][4][tid] = bR1.x;  Bs[buf][5][tid] = bR1.y;
        Bs[buf][6][tid] = bR1.z;  Bs[buf][7][tid] = bR1.w;
        __syncthreads();
        if (kt + 1 < nk) {
            aR  = __ldg((const float4*)(Ap + (size_t)(kt + 1) * 8));
            bR0 = __ldg((const float4*)(Bp + (size_t)(kt + 1) * 8));
            bR1 = __ldg((const float4*)(Bp + (size_t)(kt + 1) * 8 + 4));
        }
#pragma unroll
        for (int k = 0; k < 8; k++) {
            const float* ak = &As[buf][k][ty * 8];
            float4 a0 = *(const float4*)ak;
            float4 a1 = *(const float4*)(ak + 4);
            const double2* bk = (const double2*)&Bs[buf][k][tx * 16];
            double2 q0 = bk[0], q1 = bk[1], q2 = bk[2], q3 = bk[3];
            unsigned long long bb[8];
            bb[0] = __double_as_longlong(q0.x);  bb[1] = __double_as_longlong(q0.y);
            bb[2] = __double_as_longlong(q1.x);  bb[3] = __double_as_longlong(q1.y);
            bb[4] = __double_as_longlong(q2.x);  bb[5] = __double_as_longlong(q2.y);
            bb[6] = __double_as_longlong(q3.x);  bb[7] = __double_as_longlong(q3.y);
            float av[8] = {a0.x, a0.y, a0.z, a0.w, a1.x, a1.y, a1.z, a1.w};
#pragma unroll
            for (int i = 0; i < 8; i++) {
                unsigned long long ad = dupf(av[i]);
#pragma unroll
                for (int j = 0; j < 8; j++) FFMA2(acc[i][j], ad, bb[j]);
            }
        }
    }
    float bias16[16];
#pragma unroll
    for (int q = 0; q < 4; q++)
        *(float4*)&bias16[q * 4] = __ldg((const float4*)&bias[bn + tx * 16 + q * 4]);
#pragma unroll
    for (int i = 0; i < 8; i++) {
        float outv[16];
#pragma unroll
        for (int j = 0; j < 8; j++) {
            union { unsigned long long u; float2 f; } cv;
            cv.u = acc[i][j];
            outv[2 * j]     = cv.f.x + bias16[2 * j];
            outv[2 * j + 1] = cv.f.y + bias16[2 * j + 1];
        }
        float* crow = C + (size_t)(bm + ty * 8 + i) * N + bn + tx * 16;
#pragma unroll
        for (int q = 0; q < 4; q++) *(float4*)&crow[q * 4] = *(float4*)&outv[q * 4];
    }
}

// ---------------- persistent bidirectional LSTM layer (R7, passing) ----------------
__global__ void __launch_bounds__(NTH, 1) lstm_layer_kernel(
    const float* __restrict__ xpf, const float* __restrict__ xpb,
    const float* __restrict__ Whf, const float* __restrict__ Whb,
    float* __restrict__ hcat, unsigned* __restrict__ barbase)
{
    __shared__ __align__(16) float hsh[HID];
    __shared__ float xps[4 * JH];
    __shared__ float pre[4 * JH];
    __shared__ float csh[JH];

    const int tid = threadIdx.x;
    const int dir = blockIdx.x >> 5;
    const int cid = blockIdx.x & 31;
    const float* xp = dir ? xpb : xpf;
    const float* W  = dir ? Whb : Whf;
    unsigned* bar = barbase + dir;
    float* hbuf = g_hbuf[dir];

    const int rp   = tid >> 4;
    const int ks   = tid & 15;
    const int row0 = rp * 2, row1 = rp * 2 + 1;

    float w0r[32], w1r[32];
    {
        const int g0 = row0 >> 4, j0 = row0 & 15;
        const int g1 = row1 >> 4, j1 = row1 & 15;
        const size_t gr0 = (size_t)(g0 * HID + cid * JH + j0) * HID;
        const size_t gr1 = (size_t)(g1 * HID + cid * JH + j1) * HID;
#pragma unroll
        for (int m = 0; m < 8; m++) {
            const int k = ks * 4 + m * 64;
            float4 v0 = __ldg((const float4*)&W[gr0 + k]);
            float4 v1 = __ldg((const float4*)&W[gr1 + k]);
            w0r[4 * m + 0] = v0.x;  w0r[4 * m + 1] = v0.y;
            w0r[4 * m + 2] = v0.z;  w0r[4 * m + 3] = v0.w;
            w1r[4 * m + 0] = v1.x;  w1r[4 * m + 1] = v1.y;
            w1r[4 * m + 2] = v1.z;  w1r[4 * m + 3] = v1.w;
        }
    }
    if (tid < 128) ((float4*)hsh)[tid] = make_float4(0.f, 0.f, 0.f, 0.f);
    if (tid < JH) csh[tid] = 0.f;
    __syncthreads();

    for (int t = 0; t < SEQ; t++) {
        const int tt = dir ? (SEQ - 1 - t) : t;
        float xval = 0.f;
        if (tid < 4 * JH) {
            int g = tid >> 4, j = tid & 15;
            xval = __ldg(&xp[(size_t)tt * G4 + g * HID + cid * JH + j]);
        }
        if (t > 0) {
            if (tid == 0) {
                const unsigned target = (unsigned)NCD * (unsigned)t;
                while (atomicAdd(bar, 0u) < target) { }
                __threadfence();
            }
            __syncthreads();
            if (tid < 128) {
                const float4* hp = (const float4*)&hbuf[((t - 1) & 1) * HID];
                ((float4*)hsh)[tid] = __ldcg(hp + tid);
            }
            __syncthreads();
        }
        float a0 = 0.f, a1 = 0.f;
#pragma unroll
        for (int m = 0; m < 8; m++) {
            int k = ks * 4 + m * 64;
            float4 h4 = *(const float4*)&hsh[k];
            a0 += h4.x * w0r[4 * m] + h4.y * w0r[4 * m + 1]
                + h4.z * w0r[4 * m + 2] + h4.w * w0r[4 * m + 3];
            a1 += h4.x * w1r[4 * m] + h4.y * w1r[4 * m + 1]
                + h4.z * w1r[4 * m + 2] + h4.w * w1r[4 * m + 3];
        }
#pragma unroll
        for (int off = 8; off > 0; off >>= 1) {
            a0 += __shfl_down_sync(0xffffffffu, a0, off, 16);
            a1 += __shfl_down_sync(0xffffffffu, a1, off, 16);
        }
        if (ks == 0) { pre[row0] = a0; pre[row1] = a1; }
        if (tid < 4 * JH) xps[tid] = xval;
        __syncthreads();

        if (tid < JH) {
            const int j = tid;
            float zi = xps[j]           + pre[j];
            float zf = xps[JH + j]      + pre[JH + j];
            float zg = xps[2 * JH + j]  + pre[2 * JH + j];
            float zo = xps[3 * JH + j]  + pre[3 * JH + j];
            float ig = 1.f / (1.f + __expf(-zi));
            float fg = 1.f / (1.f + __expf(-zf));
            float gg = 2.f / (1.f + __expf(-2.f * zg)) - 1.f;
            float og = 1.f / (1.f + __expf(-zo));
            float c  = fg * csh[j] + ig * gg;
            csh[j] = c;
            float tc = 2.f / (1.f + __expf(-2.f * c)) - 1.f;
            float h  = og * tc;
            const int hj = cid * JH + j;
            __stcg(&hbuf[(t & 1) * HID + hj], h);
            hcat[(size_t)tt * (2 * HID) + dir * HID + hj] = h;
            __threadfence();
        }
        __syncthreads();
        if (tid == 0) atomicAdd(bar, 1u);
    }
}

// ---------------- bf16 mma.sync head GEMM: out[4096,32000] = A*B^T + bias -------
// hi/lo split, 3 accumulated products, fp32 accumulators in registers.
// CTA 128x128, 8 warps (4m x 2n), warp tile 32x64, K chunk 32, double buffer.
#define KC    32
#define NKC   (KH / KC)          // 32
#define RS    40                 // padded SMEM row stride (bf16 elems)
#define TSM   (128 * RS)         // bf16 elems per tile

#define MMA16816(c, a, b) \
    asm volatile("mma.sync.aligned.m16n8k16.row.col.f32.bf16.bf16.f32 " \
        "{%0,%1,%2,%3}, {%4,%5,%6,%7}, {%8,%9}, {%0,%1,%2,%3};" \
        : "+f"((c)[0]), "+f"((c)[1]), "+f"((c)[2]), "+f"((c)[3]) \
        : "r"((a)[0]), "r"((a)[1]), "r"((a)[2]), "r"((a)[3]), \
          "r"((b)[0]), "r"((b)[1]))

__global__ void __launch_bounds__(256, 1) head_mma(
    const __nv_bfloat16* __restrict__ Ahi, const __nv_bfloat16* __restrict__ Alo,
    const __nv_bfloat16* __restrict__ Bhi, const __nv_bfloat16* __restrict__ Blo,
    const float* __restrict__ bias, float* __restrict__ out)
{
    extern __shared__ __nv_bfloat16 sm[];   // [2][4][TSM]: Ahi, Alo, Bhi, Blo
    const int tid  = threadIdx.x;
    const int wid  = tid >> 5;
    const int lane = tid & 31;
    const int wm   = (wid >> 1) * 32;       // warp m offset in tile
    const int wn   = (wid & 1) * 64;        // warp n offset
    const int bm   = blockIdx.x * 128;      // m fastest -> B streams once per wave
    const int bn   = blockIdx.y * 128;

    float acc[2][8][4];
#pragma unroll
    for (int i = 0; i < 2; i++)
#pragma unroll
        for (int j = 0; j < 8; j++)
#pragma unroll
            for (int q = 0; q < 4; q++) acc[i][j][q] = 0.f;

    auto stage = [&](int kc, int buf) {
        const int k0 = kc * KC;
        __nv_bfloat16* b = sm + buf * 4 * TSM;
#pragma unroll
        for (int it = 0; it < 2; it++) {
            int idx = tid + it * 256;        // 0..511
            int row = idx >> 2;              // 0..127
            int c4  = idx & 3;               // uint4 (8 bf16) within 32-elem row
            size_t ga = (size_t)(bm + row) * KH + k0 + c4 * 8;
            size_t gb = (size_t)(bn + row) * KH + k0 + c4 * 8;
            uint32_t so = row * RS + c4 * 8;
            *(uint4*)(b + 0 * TSM + so) = __ldg((const uint4*)(Ahi + ga));
            *(uint4*)(b + 1 * TSM + so) = __ldg((const uint4*)(Alo + ga));
            *(uint4*)(b + 2 * TSM + so) = __ldg((const uint4*)(Bhi + gb));
            *(uint4*)(b + 3 * TSM + so) = __ldg((const uint4*)(Blo + gb));
        }
    };

    stage(0, 0);
    __syncthreads();

    const int g = lane >> 2;                 // 0..7
    const int q = lane & 3;                  // 0..3

    for (int kc = 0; kc < NKC; kc++) {
        if (kc + 1 < NKC) stage(kc + 1, (kc + 1) & 1);
        const __nv_bfloat16* buf = sm + (kc & 1) * 4 * TSM;
        const __nv_bfloat16* sAh = buf + 0 * TSM;
        const __nv_bfloat16* sAl = buf + 1 * TSM;
        const __nv_bfloat16* sBh = buf + 2 * TSM;
        const __nv_bfloat16* sBl = buf + 3 * TSM;
#pragma unroll
        for (int ks = 0; ks < 2; ks++) {
            const int kk = ks * 16 + q * 2;
            uint32_t ah[2][4], al[2][4];
#pragma unroll
            for (int mi = 0; mi < 2; mi++) {
                const int r = wm + mi * 16 + g;
                ah[mi][0] = *(const uint32_t*)(sAh + r * RS + kk);
                ah[mi][1] = *(const uint32_t*)(sAh + (r + 8) * RS + kk);
                ah[mi][2] = *(const uint32_t*)(sAh + r * RS + kk + 8);
                ah[mi][3] = *(const uint32_t*)(sAh + (r + 8) * RS + kk + 8);
                al[mi][0] = *(const uint32_t*)(sAl + r * RS + kk);
                al[mi][1] = *(const uint32_t*)(sAl + (r + 8) * RS + kk);
                al[mi][2] = *(const uint32_t*)(sAl + r * RS + kk + 8);
                al[mi][3] = *(const uint32_t*)(sAl + (r + 8) * RS + kk + 8);
            }
#pragma unroll
            for (int ni = 0; ni < 8; ni++) {
                const int n = wn + ni * 8 + g;
                uint32_t bh[2], bl[2];
                bh[0] = *(const uint32_t*)(sBh + n * RS + kk);
                bh[1] = *(const uint32_t*)(sBh + n * RS + kk + 8);
                bl[0] = *(const uint32_t*)(sBl + n * RS + kk);
                bl[1] = *(const uint32_t*)(sBl + n * RS + kk + 8);
#pragma unroll
                for (int mi = 0; mi < 2; mi++) {
                    MMA16816(acc[mi][ni], ah[mi], bh);
                    MMA16816(acc[mi][ni], ah[mi], bl);
                    MMA16816(acc[mi][ni], al[mi], bh);
                }
            }
        }
        __syncthreads();
    }

    // epilogue: bias + direct global store
#pragma unroll
    for (int mi = 0; mi < 2; mi++) {
        const int row0 = bm + wm + mi * 16 + g;
        float* o0 = out + (size_t)row0 * VOC + bn + wn;
        float* o1 = o0 + (size_t)8 * VOC;
#pragma unroll
        for (int ni = 0; ni < 8; ni++) {
            const int c = ni * 8 + q * 2;
            float2 bb = *(const float2*)&bias[bn + wn + c];
            float2 v0, v1;
            v0.x = acc[mi][ni][0] + bb.x;  v0.y = acc[mi][ni][1] + bb.y;
            v1.x = acc[mi][ni][2] + bb.x;  v1.y = acc[mi][ni][3] + bb.y;
            *(float2*)(o0 + c) = v0;
            *(float2*)(o1 + c) = v1;
        }
    }
}

// ---------------- launch ----------------
extern "C" void kernel_launch(void* const* d_in, const int* in_sizes, int n_in,
                              void* d_out, int out_size)
{
    (void)in_sizes; (void)n_in; (void)out_size;
    const int*   idx   = (const int*)  d_in[0];
    const float* ew    = (const float*)d_in[1];
    const float* Wih0f = (const float*)d_in[2];
    const float* Whh0f = (const float*)d_in[3];
    const float* b0f   = (const float*)d_in[4];
    const float* Wih0b = (const float*)d_in[5];
    const float* Whh0b = (const float*)d_in[6];
    const float* b0b   = (const float*)d_in[7];
    const float* Wih1f = (const float*)d_in[8];
    const float* Whh1f = (const float*)d_in[9];
    const float* b1f   = (const float*)d_in[10];
    const float* Wih1b = (const float*)d_in[11];
    const float* Whh1b = (const float*)d_in[12];
    const float* b1b   = (const float*)d_in[13];
    const float* Wlin  = (const float*)d_in[14];
    const float* blin  = (const float*)d_in[15];
    float* out = (float*)d_out;

    float *x0, *xpf, *xpb, *h0, *h1; unsigned* bars;
    __nv_bfloat16 *whi, *wlo, *ahi, *alo;
    cudaGetSymbolAddress((void**)&x0,  g_x0);
    cudaGetSymbolAddress((void**)&xpf, g_xpf);
    cudaGetSymbolAddress((void**)&xpb, g_xpb);
    cudaGetSymbolAddress((void**)&h0,  g_h0);
    cudaGetSymbolAddress((void**)&h1,  g_h1);
    cudaGetSymbolAddress((void**)&bars, g_bar);
    cudaGetSymbolAddress((void**)&whi, g_whi);
    cudaGetSymbolAddress((void**)&wlo, g_wlo);
    cudaGetSymbolAddress((void**)&ahi, g_ahi);
    cudaGetSymbolAddress((void**)&alo, g_alo);

    const int head_smem = 2 * 4 * TSM * (int)sizeof(__nv_bfloat16);   // 81920
    cudaFuncSetAttribute(head_mma, cudaFuncAttributeMaxDynamicSharedMemorySize, head_smem);

    // 0) embed + counter reset
    embed_kernel<<<SEQ, 128>>>(idx, ew);
    // 1) Wlin split (no deps on LSTM)
    split_bf16<<<(VOC * KH / 4) / 256, 256>>>(Wlin, whi, wlo);
    // 2,3) layer-0 xproj
    {
        dim3 grid(G4 / 256, SEQ / 128);
        gemm_nt_bias<<<grid, 256>>>(x0, Wih0f, b0f, xpf, SEQ, G4, HID);
        gemm_nt_bias<<<grid, 256>>>(x0, Wih0b, b0b, xpb, SEQ, G4, HID);
    }
    // 4) layer-0 recurrence
    lstm_layer_kernel<<<2 * NCD, NTH>>>(xpf, xpb, Whh0f, Whh0b, h0, bars);
    // 5,6) layer-1 xproj
    {
        dim3 grid(G4 / 256, SEQ / 128);
        gemm_nt_bias<<<grid, 256>>>(h0, Wih1f, b1f, xpf, SEQ, G4, 2 * HID);
        gemm_nt_bias<<<grid, 256>>>(h0, Wih1b, b1b, xpb, SEQ, G4, 2 * HID);
    }
    // 7) layer-1 recurrence
    lstm_layer_kernel<<<2 * NCD, NTH>>>(xpf, xpb, Whh1f, Whh1b, h1, bars + 2);
    // 8) h1 split
    split_bf16<<<(SEQ * KH / 4) / 256, 256>>>(h1, ahi, alo);
    // 9) tensor-core head GEMM (m fastest in grid.x for B-streaming reuse)
    {
        dim3 grid(SEQ / 128, VOC / 128);     // 32 x 250
        head_mma<<<grid, 256, head_smem>>>(ahi, alo, whi, wlo, blin, out);
    }
}

// round 10
// speedup vs baseline: 1.6873x; 1.2959x over previous
#include <cuda_runtime.h>
#include <cuda_bf16.h>
#include <cstdint>

#define SEQ    4096
#define HID    512
#define G4     2048          // 4*HID
#define NCD    32            // CTAs per direction in the recurrence
#define NTH    512           // threads per LSTM CTA
#define JH     16            // h outputs per CTA (64 gate rows)
#define VOC    32000
#define KH     1024          // head GEMM K (2*HID)

// ---------------- scratch (device globals; no allocation allowed) ----------------
static __device__ __align__(16) float    g_x0 [SEQ * HID];
static __device__ __align__(16) float    g_xpf[SEQ * G4];
static __device__ __align__(16) float    g_xpb[SEQ * G4];
static __device__ __align__(16) float    g_h0 [SEQ * 2 * HID];
static __device__ __align__(16) float    g_h1 [SEQ * 2 * HID];
static __device__ __align__(16) float    g_hbuf[2][2 * HID];
static __device__ __align__(16) unsigned g_bar[4];
// bf16 hi/lo splits
static __device__ __align__(16) __nv_bfloat16 g_whi [VOC * KH];
static __device__ __align__(16) __nv_bfloat16 g_wlo [VOC * KH];
static __device__ __align__(16) __nv_bfloat16 g_ahi [SEQ * KH];
static __device__ __align__(16) __nv_bfloat16 g_alo [SEQ * KH];
static __device__ __align__(16) __nv_bfloat16 g_w0fhi[G4 * HID], g_w0flo[G4 * HID];
static __device__ __align__(16) __nv_bfloat16 g_w0bhi[G4 * HID], g_w0blo[G4 * HID];
static __device__ __align__(16) __nv_bfloat16 g_w1fhi[G4 * KH],  g_w1flo[G4 * KH];
static __device__ __align__(16) __nv_bfloat16 g_w1bhi[G4 * KH],  g_w1blo[G4 * KH];

// ---------------- sync helpers (CG grid-sync protocol) ----------------
__device__ __forceinline__ unsigned ld_acq(const unsigned* p) {
    unsigned v;
    asm volatile("ld.acquire.gpu.global.u32 %0, [%1];" : "=r"(v) : "l"(p) : "memory");
    return v;
}
__device__ __forceinline__ void red_rel_add(unsigned* p, unsigned v) {
    asm volatile("red.release.gpu.global.add.u32 [%0], %1;" :: "l"(p), "r"(v) : "memory");
}

// ---------------- embed (+ counter reset) ----------------
__global__ void embed_kernel(const int* __restrict__ idx, const float* __restrict__ ew) {
    if (blockIdx.x == 0 && threadIdx.x < 4) g_bar[threadIdx.x] = 0u;
    int s = blockIdx.x;
    int r = idx[s];
    ((float4*)(g_x0 + (size_t)s * HID))[threadIdx.x] =
        ((const float4*)(ew + (size_t)r * HID))[threadIdx.x];
}

// ---------------- fp32 -> bf16 hi/lo split ----------------
__global__ void split_bf16(const float* __restrict__ src,
                           __nv_bfloat16* __restrict__ hi, __nv_bfloat16* __restrict__ lo) {
    int i = blockIdx.x * 256 + threadIdx.x;        // one float4 per thread
    float4 v = __ldg((const float4*)src + i);
    __nv_bfloat16 h0 = __float2bfloat16_rn(v.x), h1 = __float2bfloat16_rn(v.y);
    __nv_bfloat16 h2 = __float2bfloat16_rn(v.z), h3 = __float2bfloat16_rn(v.w);
    __nv_bfloat16 l0 = __float2bfloat16_rn(v.x - __bfloat162float(h0));
    __nv_bfloat16 l1 = __float2bfloat16_rn(v.y - __bfloat162float(h1));
    __nv_bfloat16 l2 = __float2bfloat16_rn(v.z - __bfloat162float(h2));
    __nv_bfloat16 l3 = __float2bfloat16_rn(v.w - __bfloat162float(h3));
    ushort4 hv = make_ushort4(*(unsigned short*)&h0, *(unsigned short*)&h1,
                              *(unsigned short*)&h2, *(unsigned short*)&h3);
    ushort4 lv = make_ushort4(*(unsigned short*)&l0, *(unsigned short*)&l1,
                              *(unsigned short*)&l2, *(unsigned short*)&l3);
    ((ushort4*)hi)[i] = hv;
    ((ushort4*)lo)[i] = lv;
}

// ---------------- persistent bidirectional LSTM layer ----------------
// R7 kernel with the sync swapped to the CG grid-sync protocol:
// producers: stores -> bar.sync -> tid0 red.release; consumers: tid0 ld.acquire spin -> bar.sync.
__global__ void __launch_bounds__(NTH, 1) lstm_layer_kernel(
    const float* __restrict__ xpf, const float* __restrict__ xpb,
    const float* __restrict__ Whf, const float* __restrict__ Whb,
    float* __restrict__ hcat, unsigned* __restrict__ barbase)
{
    __shared__ __align__(16) float hsh[HID];
    __shared__ float xps[4 * JH];
    __shared__ float pre[4 * JH];
    __shared__ float csh[JH];

    const int tid = threadIdx.x;
    const int dir = blockIdx.x >> 5;
    const int cid = blockIdx.x & 31;
    const float* xp = dir ? xpb : xpf;
    const float* W  = dir ? Whb : Whf;
    unsigned* bar = barbase + dir;
    float* hbuf = g_hbuf[dir];

    const int rp   = tid >> 4;
    const int ks   = tid & 15;
    const int row0 = rp * 2, row1 = rp * 2 + 1;

    float w0r[32], w1r[32];
    {
        const int g0 = row0 >> 4, j0 = row0 & 15;
        const int g1 = row1 >> 4, j1 = row1 & 15;
        const size_t gr0 = (size_t)(g0 * HID + cid * JH + j0) * HID;
        const size_t gr1 = (size_t)(g1 * HID + cid * JH + j1) * HID;
#pragma unroll
        for (int m = 0; m < 8; m++) {
            const int k = ks * 4 + m * 64;
            float4 v0 = __ldg((const float4*)&W[gr0 + k]);
            float4 v1 = __ldg((const float4*)&W[gr1 + k]);
            w0r[4 * m + 0] = v0.x;  w0r[4 * m + 1] = v0.y;
            w0r[4 * m + 2] = v0.z;  w0r[4 * m + 3] = v0.w;
            w1r[4 * m + 0] = v1.x;  w1r[4 * m + 1] = v1.y;
            w1r[4 * m + 2] = v1.z;  w1r[4 * m + 3] = v1.w;
        }
    }
    if (tid < 128) ((float4*)hsh)[tid] = make_float4(0.f, 0.f, 0.f, 0.f);
    if (tid < JH) csh[tid] = 0.f;
    __syncthreads();

    for (int t = 0; t < SEQ; t++) {
        const int tt = dir ? (SEQ - 1 - t) : t;
        // prefetch this step's xproj values (immutable; includes bias)
        float xval = 0.f;
        if (tid < 4 * JH) {
            int g = tid >> 4, j = tid & 15;
            xval = __ldg(&xp[(size_t)tt * G4 + g * HID + cid * JH + j]);
        }
        if (t > 0) {
            if (tid == 0) {
                const unsigned target = (unsigned)NCD * (unsigned)t;
                while (ld_acq(bar) < target) { }   // acquire load spin (no RMW)
            }
            __syncthreads();
            if (tid < 128) {
                const float4* hp = (const float4*)&hbuf[((t - 1) & 1) * HID];
                ((float4*)hsh)[tid] = __ldcg(hp + tid);   // L2 (bypass stale L1)
            }
            __syncthreads();
        }
        float a0 = 0.f, a1 = 0.f;
#pragma unroll
        for (int m = 0; m < 8; m++) {
            int k = ks * 4 + m * 64;
            float4 h4 = *(const float4*)&hsh[k];
            a0 += h4.x * w0r[4 * m] + h4.y * w0r[4 * m + 1]
                + h4.z * w0r[4 * m + 2] + h4.w * w0r[4 * m + 3];
            a1 += h4.x * w1r[4 * m] + h4.y * w1r[4 * m + 1]
                + h4.z * w1r[4 * m + 2] + h4.w * w1r[4 * m + 3];
        }
#pragma unroll
        for (int off = 8; off > 0; off >>= 1) {
            a0 += __shfl_down_sync(0xffffffffu, a0, off, 16);
            a1 += __shfl_down_sync(0xffffffffu, a1, off, 16);
        }
        if (ks == 0) { pre[row0] = a0; pre[row1] = a1; }
        if (tid < 4 * JH) xps[tid] = xval;
        __syncthreads();

        if (tid < JH) {
            const int j = tid;
            float zi = xps[j]           + pre[j];
            float zf = xps[JH + j]      + pre[JH + j];
            float zg = xps[2 * JH + j]  + pre[2 * JH + j];
            float zo = xps[3 * JH + j]  + pre[3 * JH + j];
            float ig = 1.f / (1.f + __expf(-zi));
            float fg = 1.f / (1.f + __expf(-zf));
            float gg = 2.f / (1.f + __expf(-2.f * zg)) - 1.f;
            float og = 1.f / (1.f + __expf(-zo));
            float c  = fg * csh[j] + ig * gg;
            csh[j] = c;
            float tc = 2.f / (1.f + __expf(-2.f * c)) - 1.f;
            float h  = og * tc;
            const int hj = cid * JH + j;
            __stcg(&hbuf[(t & 1) * HID + hj], h);             // broadcast state
            hcat[(size_t)tt * (2 * HID) + dir * HID + hj] = h; // layer output (no fence needed)
        }
        __syncthreads();                                       // writers' stores precede release
        if (tid == 0) red_rel_add(bar, 1u);                    // release increment (no return)
    }
}

// ---------------- bf16 mma.sync GEMM: out[M,N] = A[M,K]*B[N,K]^T + bias ----------
// hi/lo split, 3 accumulated products, fp32 register accumulators.
// CTA 128x128, 8 warps (4m x 2n), warp tile 32x64, K chunk 32, double buffer.
#define KC    32
#define RS    40                 // padded SMEM row stride (bf16 elems)
#define TSM   (128 * RS)         // bf16 elems per tile

#define MMA16816(c, a, b) \
    asm volatile("mma.sync.aligned.m16n8k16.row.col.f32.bf16.bf16.f32 " \
        "{%0,%1,%2,%3}, {%4,%5,%6,%7}, {%8,%9}, {%0,%1,%2,%3};" \
        : "+f"((c)[0]), "+f"((c)[1]), "+f"((c)[2]), "+f"((c)[3]) \
        : "r"((a)[0]), "r"((a)[1]), "r"((a)[2]), "r"((a)[3]), \
          "r"((b)[0]), "r"((b)[1]))

__global__ void __launch_bounds__(256, 1) mma_gemm(
    const __nv_bfloat16* __restrict__ Ahi, const __nv_bfloat16* __restrict__ Alo,
    const __nv_bfloat16* __restrict__ Bhi, const __nv_bfloat16* __restrict__ Blo,
    const float* __restrict__ bias, float* __restrict__ out,
    int K, int ldout)
{
    extern __shared__ __nv_bfloat16 sm[];   // [2][4][TSM]: Ahi, Alo, Bhi, Blo
    const int tid  = threadIdx.x;
    const int wid  = tid >> 5;
    const int lane = tid & 31;
    const int wm   = (wid >> 1) * 32;
    const int wn   = (wid & 1) * 64;
    const int bm   = blockIdx.x * 128;      // m fastest -> B streams once per wave
    const int bn   = blockIdx.y * 128;
    const int nkc  = K / KC;

    float acc[2][8][4];
#pragma unroll
    for (int i = 0; i < 2; i++)
#pragma unroll
        for (int j = 0; j < 8; j++)
#pragma unroll
            for (int q = 0; q < 4; q++) acc[i][j][q] = 0.f;

    auto stage = [&](int kc, int buf) {
        const int k0 = kc * KC;
        __nv_bfloat16* b = sm + buf * 4 * TSM;
#pragma unroll
        for (int it = 0; it < 2; it++) {
            int idx = tid + it * 256;        // 0..511
            int row = idx >> 2;              // 0..127
            int c4  = idx & 3;
            size_t ga = (size_t)(bm + row) * K + k0 + c4 * 8;
            size_t gb = (size_t)(bn + row) * K + k0 + c4 * 8;
            uint32_t so = row * RS + c4 * 8;
            *(uint4*)(b + 0 * TSM + so) = __ldg((const uint4*)(Ahi + ga));
            *(uint4*)(b + 1 * TSM + so) = __ldg((const uint4*)(Alo + ga));
            *(uint4*)(b + 2 * TSM + so) = __ldg((const uint4*)(Bhi + gb));
            *(uint4*)(b + 3 * TSM + so) = __ldg((const uint4*)(Blo + gb));
        }
    };

    stage(0, 0);
    __syncthreads();

    const int g = lane >> 2;
    const int q = lane & 3;

    for (int kc = 0; kc < nkc; kc++) {
        if (kc + 1 < nkc) stage(kc + 1, (kc + 1) & 1);
        const __nv_bfloat16* buf = sm + (kc & 1) * 4 * TSM;
        const __nv_bfloat16* sAh = buf + 0 * TSM;
        const __nv_bfloat16* sAl = buf + 1 * TSM;
        const __nv_bfloat16* sBh = buf + 2 * TSM;
        const __nv_bfloat16* sBl = buf + 3 * TSM;
#pragma unroll
        for (int ks = 0; ks < 2; ks++) {
            const int kk = ks * 16 + q * 2;
            uint32_t ah[2][4], al[2][4];
#pragma unroll
            for (int mi = 0; mi < 2; mi++) {
                const int r = wm + mi * 16 + g;
                ah[mi][0] = *(const uint32_t*)(sAh + r * RS + kk);
                ah[mi][1] = *(const uint32_t*)(sAh + (r + 8) * RS + kk);
                ah[mi][2] = *(const uint32_t*)(sAh + r * RS + kk + 8);
                ah[mi][3] = *(const uint32_t*)(sAh + (r + 8) * RS + kk + 8);
                al[mi][0] = *(const uint32_t*)(sAl + r * RS + kk);
                al[mi][1] = *(const uint32_t*)(sAl + (r + 8) * RS + kk);
                al[mi][2] = *(const uint32_t*)(sAl + r * RS + kk + 8);
                al[mi][3] = *(const uint32_t*)(sAl + (r + 8) * RS + kk + 8);
            }
#pragma unroll
            for (int ni = 0; ni < 8; ni++) {
                const int n = wn + ni * 8 + g;
                uint32_t bh[2], bl[2];
                bh[0] = *(const uint32_t*)(sBh + n * RS + kk);
                bh[1] = *(const uint32_t*)(sBh + n * RS + kk + 8);
                bl[0] = *(const uint32_t*)(sBl + n * RS + kk);
                bl[1] = *(const uint32_t*)(sBl + n * RS + kk + 8);
#pragma unroll
                for (int mi = 0; mi < 2; mi++) {
                    MMA16816(acc[mi][ni], ah[mi], bh);
                    MMA16816(acc[mi][ni], ah[mi], bl);
                    MMA16816(acc[mi][ni], al[mi], bh);
                }
            }
        }
        __syncthreads();
    }

    // epilogue: bias + direct global store
#pragma unroll
    for (int mi = 0; mi < 2; mi++) {
        const int row0 = bm + wm + mi * 16 + g;
        float* o0 = out + (size_t)row0 * ldout + bn + wn;
        float* o1 = o0 + (size_t)8 * ldout;
#pragma unroll
        for (int ni = 0; ni < 8; ni++) {
            const int c = ni * 8 + q * 2;
            float2 bb = *(const float2*)&bias[bn + wn + c];
            float2 v0, v1;
            v0.x = acc[mi][ni][0] + bb.x;  v0.y = acc[mi][ni][1] + bb.y;
            v1.x = acc[mi][ni][2] + bb.x;  v1.y = acc[mi][ni][3] + bb.y;
            *(float2*)(o0 + c) = v0;
            *(float2*)(o1 + c) = v1;
        }
    }
}

// ---------------- launch ----------------
extern "C" void kernel_launch(void* const* d_in, const int* in_sizes, int n_in,
                              void* d_out, int out_size)
{
    (void)in_sizes; (void)n_in; (void)out_size;
    const int*   idx   = (const int*)  d_in[0];
    const float* ew    = (const float*)d_in[1];
    const float* Wih0f = (const float*)d_in[2];
    const float* Whh0f = (const float*)d_in[3];
    const float* b0f   = (const float*)d_in[4];
    const float* Wih0b = (const float*)d_in[5];
    const float* Whh0b = (const float*)d_in[6];
    const float* b0b   = (const float*)d_in[7];
    const float* Wih1f = (const float*)d_in[8];
    const float* Whh1f = (const float*)d_in[9];
    const float* b1f   = (const float*)d_in[10];
    const float* Wih1b = (const float*)d_in[11];
    const float* Whh1b = (const float*)d_in[12];
    const float* b1b   = (const float*)d_in[13];
    const float* Wlin  = (const float*)d_in[14];
    const float* blin  = (const float*)d_in[15];
    float* out = (float*)d_out;

    float *x0, *xpf, *xpb, *h0, *h1; unsigned* bars;
    __nv_bfloat16 *whi, *wlo, *ahi, *alo;
    __nv_bfloat16 *w0fh, *w0fl, *w0bh, *w0bl, *w1fh, *w1fl, *w1bh, *w1bl;
    cudaGetSymbolAddress((void**)&x0,  g_x0);
    cudaGetSymbolAddress((void**)&xpf, g_xpf);
    cudaGetSymbolAddress((void**)&xpb, g_xpb);
    cudaGetSymbolAddress((void**)&h0,  g_h0);
    cudaGetSymbolAddress((void**)&h1,  g_h1);
    cudaGetSymbolAddress((void**)&bars, g_bar);
    cudaGetSymbolAddress((void**)&whi, g_whi);
    cudaGetSymbolAddress((void**)&wlo, g_wlo);
    cudaGetSymbolAddress((void**)&ahi, g_ahi);
    cudaGetSymbolAddress((void**)&alo, g_alo);
    cudaGetSymbolAddress((void**)&w0fh, g_w0fhi);  cudaGetSymbolAddress((void**)&w0fl, g_w0flo);
    cudaGetSymbolAddress((void**)&w0bh, g_w0bhi);  cudaGetSymbolAddress((void**)&w0bl, g_w0blo);
    cudaGetSymbolAddress((void**)&w1fh, g_w1fhi);  cudaGetSymbolAddress((void**)&w1fl, g_w1flo);
    cudaGetSymbolAddress((void**)&w1bh, g_w1bhi);  cudaGetSymbolAddress((void**)&w1bl, g_w1blo);

    const int gemm_smem = 2 * 4 * TSM * (int)sizeof(__nv_bfloat16);   // 81920
    cudaFuncSetAttribute(mma_gemm, cudaFuncAttributeMaxDynamicSharedMemorySize, gemm_smem);

    // 0) embed + counter reset
    embed_kernel<<<SEQ, 128>>>(idx, ew);
    // 1) weight/activation splits for layer-0 xproj + head weights
    split_bf16<<<(VOC * KH / 4) / 256, 256>>>(Wlin, whi, wlo);
    split_bf16<<<(SEQ * HID / 4) / 256, 256>>>(x0, ahi, alo);
    split_bf16<<<(G4 * HID / 4) / 256, 256>>>(Wih0f, w0fh, w0fl);
    split_bf16<<<(G4 * HID / 4) / 256, 256>>>(Wih0b, w0bh, w0bl);
    // 2) layer-0 xproj (M=SEQ, N=G4, K=HID)
    {
        dim3 grid(SEQ / 128, G4 / 128);      // 32 x 16
        mma_gemm<<<grid, 256, gemm_smem>>>(ahi, alo, w0fh, w0fl, b0f, xpf, HID, G4);
        mma_gemm<<<grid, 256, gemm_smem>>>(ahi, alo, w0bh, w0bl, b0b, xpb, HID, G4);
    }
    // 3) layer-0 recurrence
    lstm_layer_kernel<<<2 * NCD, NTH>>>(xpf, xpb, Whh0f, Whh0b, h0, bars);
    // 4) splits for layer-1 xproj
    split_bf16<<<(SEQ * KH / 4) / 256, 256>>>(h0, ahi, alo);
    split_bf16<<<(G4 * KH / 4) / 256, 256>>>(Wih1f, w1fh, w1fl);
    split_bf16<<<(G4 * KH / 4) / 256, 256>>>(Wih1b, w1bh, w1bl);
    // 5) layer-1 xproj (K=KH)
    {
        dim3 grid(SEQ / 128, G4 / 128);
        mma_gemm<<<grid, 256, gemm_smem>>>(ahi, alo, w1fh, w1fl, b1f, xpf, KH, G4);
        mma_gemm<<<grid, 256, gemm_smem>>>(ahi, alo, w1bh, w1bl, b1b, xpb, KH, G4);
    }
    // 6) layer-1 recurrence
    lstm_layer_kernel<<<2 * NCD, NTH>>>(xpf, xpb, Whh1f, Whh1b, h1, bars + 2);
    // 7) head
    split_bf16<<<(SEQ * KH / 4) / 256, 256>>>(h1, ahi, alo);
    {
        dim3 grid(SEQ / 128, VOC / 128);     // 32 x 250
        mma_gemm<<<grid, 256, gemm_smem>>>(ahi, alo, whi, wlo, blin, out, KH, VOC);
    }
}

// round 11
// speedup vs baseline: 2.0203x; 1.1973x over previous
#include <cuda_runtime.h>
#include <cuda_bf16.h>
#include <cstdint>

#define SEQ    4096
#define HID    512
#define G4     2048          // 4*HID
#define NCD    32            // CTAs per direction in the recurrence
#define NTH    512           // threads per LSTM CTA
#define JH     16            // h outputs per CTA (64 gate rows)
#define VOC    32000
#define KH     1024          // head GEMM K (2*HID)

// ---------------- scratch (device globals; no allocation allowed) ----------------
static __device__ __align__(16) float    g_x0 [SEQ * HID];
static __device__ __align__(16) float    g_xpf[SEQ * G4];
static __device__ __align__(16) float    g_xpb[SEQ * G4];
static __device__ __align__(16) float    g_h0 [SEQ * 2 * HID];
static __device__ __align__(16) float    g_h1 [SEQ * 2 * HID];
// bf16 hi/lo splits
static __device__ __align__(16) __nv_bfloat16 g_whi [VOC * KH];
static __device__ __align__(16) __nv_bfloat16 g_wlo [VOC * KH];
static __device__ __align__(16) __nv_bfloat16 g_ahi [SEQ * KH];
static __device__ __align__(16) __nv_bfloat16 g_alo [SEQ * KH];
static __device__ __align__(16) __nv_bfloat16 g_w0fhi[G4 * HID], g_w0flo[G4 * HID];
static __device__ __align__(16) __nv_bfloat16 g_w0bhi[G4 * HID], g_w0blo[G4 * HID];
static __device__ __align__(16) __nv_bfloat16 g_w1fhi[G4 * KH],  g_w1flo[G4 * KH];
static __device__ __align__(16) __nv_bfloat16 g_w1bhi[G4 * KH],  g_w1blo[G4 * KH];

// ---------------- embed ----------------
__global__ void embed_kernel(const int* __restrict__ idx, const float* __restrict__ ew) {
    int s = blockIdx.x;
    int r = idx[s];
    ((float4*)(g_x0 + (size_t)s * HID))[threadIdx.x] =
        ((const float4*)(ew + (size_t)r * HID))[threadIdx.x];
}

// ---------------- canary fill (NaN) for the data-is-flag h exchange ----------------
__global__ void canary_fill(float* __restrict__ p) {
    const unsigned NANP = 0x7FC00000u;
    uint4 v = make_uint4(NANP, NANP, NANP, NANP);
    ((uint4*)p)[(size_t)blockIdx.x * 256 + threadIdx.x] = v;
}

// ---------------- fp32 -> bf16 hi/lo split ----------------
__global__ void split_bf16(const float* __restrict__ src,
                           __nv_bfloat16* __restrict__ hi, __nv_bfloat16* __restrict__ lo) {
    int i = blockIdx.x * 256 + threadIdx.x;        // one float4 per thread
    float4 v = __ldg((const float4*)src + i);
    __nv_bfloat16 h0 = __float2bfloat16_rn(v.x), h1 = __float2bfloat16_rn(v.y);
    __nv_bfloat16 h2 = __float2bfloat16_rn(v.z), h3 = __float2bfloat16_rn(v.w);
    __nv_bfloat16 l0 = __float2bfloat16_rn(v.x - __bfloat162float(h0));
    __nv_bfloat16 l1 = __float2bfloat16_rn(v.y - __bfloat162float(h1));
    __nv_bfloat16 l2 = __float2bfloat16_rn(v.z - __bfloat162float(h2));
    __nv_bfloat16 l3 = __float2bfloat16_rn(v.w - __bfloat162float(h3));
    ushort4 hv = make_ushort4(*(unsigned short*)&h0, *(unsigned short*)&h1,
                              *(unsigned short*)&h2, *(unsigned short*)&h3);
    ushort4 lv = make_ushort4(*(unsigned short*)&l0, *(unsigned short*)&l1,
                              *(unsigned short*)&l2, *(unsigned short*)&l3);
    ((ushort4*)hi)[i] = hv;
    ((ushort4*)lo)[i] = lv;
}

// ---------------- persistent bidirectional LSTM layer ----------------
// Data-is-flag sync: hcat is canary(NaN)-prefilled; producers store h straight to
// hcat; consumers poll the 512 h floats of step t-1 directly (ld.global.cg) and
// proceed once all are non-NaN — the poll result IS the data (one L2 trip).
__device__ __forceinline__ float4 ldcg_f4(const float4* p) {
    float4 v;
    asm volatile("ld.global.cg.v4.f32 {%0,%1,%2,%3}, [%4];"
                 : "=f"(v.x), "=f"(v.y), "=f"(v.z), "=f"(v.w) : "l"(p) : "memory");
    return v;
}

__global__ void __launch_bounds__(NTH, 1) lstm_layer_kernel(
    const float* __restrict__ xpf, const float* __restrict__ xpb,
    const float* __restrict__ Whf, const float* __restrict__ Whb,
    float* __restrict__ hcat)
{
    __shared__ __align__(16) float hsh[HID];
    __shared__ float xps[4 * JH];
    __shared__ float pre[4 * JH];
    __shared__ float csh[JH];

    const int tid = threadIdx.x;
    const int dir = blockIdx.x >> 5;
    const int cid = blockIdx.x & 31;
    const float* xp = dir ? xpb : xpf;
    const float* W  = dir ? Whb : Whf;

    const int rp   = tid >> 4;
    const int ks   = tid & 15;
    const int row0 = rp * 2, row1 = rp * 2 + 1;

    float w0r[32], w1r[32];
    {
        const int g0 = row0 >> 4, j0 = row0 & 15;
        const int g1 = row1 >> 4, j1 = row1 & 15;
        const size_t gr0 = (size_t)(g0 * HID + cid * JH + j0) * HID;
        const size_t gr1 = (size_t)(g1 * HID + cid * JH + j1) * HID;
#pragma unroll
        for (int m = 0; m < 8; m++) {
            const int k = ks * 4 + m * 64;
            float4 v0 = __ldg((const float4*)&W[gr0 + k]);
            float4 v1 = __ldg((const float4*)&W[gr1 + k]);
            w0r[4 * m + 0] = v0.x;  w0r[4 * m + 1] = v0.y;
            w0r[4 * m + 2] = v0.z;  w0r[4 * m + 3] = v0.w;
            w1r[4 * m + 0] = v1.x;  w1r[4 * m + 1] = v1.y;
            w1r[4 * m + 2] = v1.z;  w1r[4 * m + 3] = v1.w;
        }
    }
    if (tid < 128) ((float4*)hsh)[tid] = make_float4(0.f, 0.f, 0.f, 0.f);
    if (tid < JH) csh[tid] = 0.f;
    __syncthreads();

    for (int t = 0; t < SEQ; t++) {
        const int tt = dir ? (SEQ - 1 - t) : t;
        // prefetch this step's xproj values (immutable; includes bias)
        float xval = 0.f;
        if (tid < 4 * JH) {
            int g = tid >> 4, j = tid & 15;
            xval = __ldg(&xp[(size_t)tt * G4 + g * HID + cid * JH + j]);
        }
        if (t > 0) {
            const int ttp = dir ? (tt + 1) : (tt - 1);
            const float4* hrow = (const float4*)&hcat[(size_t)ttp * (2 * HID) + dir * HID];
            float4 h4 = make_float4(0.f, 0.f, 0.f, 0.f);
            for (;;) {
                bool ok = true;
                if (tid < 128) {
                    h4 = ldcg_f4(hrow + tid);
                    // canary is NaN; real h is always finite
                    ok = (h4.x == h4.x) && (h4.y == h4.y) && (h4.z == h4.z) && (h4.w == h4.w);
                }
                if (__syncthreads_and(ok)) break;
            }
            if (tid < 128) ((float4*)hsh)[tid] = h4;
            __syncthreads();
        }
        // matvec: pre[r] = sum_k h[k] * Whh[r][k], 2 rows per thread, strided k
        float a0 = 0.f, a1 = 0.f;
#pragma unroll
        for (int m = 0; m < 8; m++) {
            int k = ks * 4 + m * 64;
            float4 h4 = *(const float4*)&hsh[k];
            a0 += h4.x * w0r[4 * m] + h4.y * w0r[4 * m + 1]
                + h4.z * w0r[4 * m + 2] + h4.w * w0r[4 * m + 3];
            a1 += h4.x * w1r[4 * m] + h4.y * w1r[4 * m + 1]
                + h4.z * w1r[4 * m + 2] + h4.w * w1r[4 * m + 3];
        }
#pragma unroll
        for (int off = 8; off > 0; off >>= 1) {
            a0 += __shfl_down_sync(0xffffffffu, a0, off, 16);
            a1 += __shfl_down_sync(0xffffffffu, a1, off, 16);
        }
        if (ks == 0) { pre[row0] = a0; pre[row1] = a1; }
        if (tid < 4 * JH) xps[tid] = xval;
        __syncthreads();

        if (tid < JH) {
            const int j = tid;
            float zi = xps[j]           + pre[j];
            float zf = xps[JH + j]      + pre[JH + j];
            float zg = xps[2 * JH + j]  + pre[2 * JH + j];
            float zo = xps[3 * JH + j]  + pre[3 * JH + j];
            float ig = 1.f / (1.f + __expf(-zi));
            float fg = 1.f / (1.f + __expf(-zf));
            float gg = 2.f / (1.f + __expf(-2.f * zg)) - 1.f;
            float og = 1.f / (1.f + __expf(-zo));
            float c  = fg * csh[j] + ig * gg;
            csh[j] = c;
            float tc = 2.f / (1.f + __expf(-2.f * c)) - 1.f;
            float h  = og * tc;
            const int hj = cid * JH + j;
            __stcg(&hcat[(size_t)tt * (2 * HID) + dir * HID + hj], h);  // data IS the flag
        }
        __syncthreads();
    }
}

// ---------------- bf16 mma.sync GEMM: out[M,N] = A[M,K]*B[N,K]^T + bias ----------
#define KC    32
#define RS    40                 // padded SMEM row stride (bf16 elems)
#define TSM   (128 * RS)         // bf16 elems per tile

#define MMA16816(c, a, b) \
    asm volatile("mma.sync.aligned.m16n8k16.row.col.f32.bf16.bf16.f32 " \
        "{%0,%1,%2,%3}, {%4,%5,%6,%7}, {%8,%9}, {%0,%1,%2,%3};" \
        : "+f"((c)[0]), "+f"((c)[1]), "+f"((c)[2]), "+f"((c)[3]) \
        : "r"((a)[0]), "r"((a)[1]), "r"((a)[2]), "r"((a)[3]), \
          "r"((b)[0]), "r"((b)[1]))

__global__ void __launch_bounds__(256, 1) mma_gemm(
    const __nv_bfloat16* __restrict__ Ahi, const __nv_bfloat16* __restrict__ Alo,
    const __nv_bfloat16* __restrict__ Bhi, const __nv_bfloat16* __restrict__ Blo,
    const float* __restrict__ bias, float* __restrict__ out,
    int K, int ldout)
{
    extern __shared__ __nv_bfloat16 sm[];   // [2][4][TSM]: Ahi, Alo, Bhi, Blo
    const int tid  = threadIdx.x;
    const int wid  = tid >> 5;
    const int lane = tid & 31;
    const int wm   = (wid >> 1) * 32;
    const int wn   = (wid & 1) * 64;
    const int bm   = blockIdx.x * 128;      // m fastest -> B streams once per wave
    const int bn   = blockIdx.y * 128;
    const int nkc  = K / KC;

    float acc[2][8][4];
#pragma unroll
    for (int i = 0; i < 2; i++)
#pragma unroll
        for (int j = 0; j < 8; j++)
#pragma unroll
            for (int q = 0; q < 4; q++) acc[i][j][q] = 0.f;

    auto stage = [&](int kc, int buf) {
        const int k0 = kc * KC;
        __nv_bfloat16* b = sm + buf * 4 * TSM;
#pragma unroll
        for (int it = 0; it < 2; it++) {
            int idx = tid + it * 256;        // 0..511
            int row = idx >> 2;              // 0..127
            int c4  = idx & 3;
            size_t ga = (size_t)(bm + row) * K + k0 + c4 * 8;
            size_t gb = (size_t)(bn + row) * K + k0 + c4 * 8;
            uint32_t so = row * RS + c4 * 8;
            *(uint4*)(b + 0 * TSM + so) = __ldg((const uint4*)(Ahi + ga));
            *(uint4*)(b + 1 * TSM + so) = __ldg((const uint4*)(Alo + ga));
            *(uint4*)(b + 2 * TSM + so) = __ldg((const uint4*)(Bhi + gb));
            *(uint4*)(b + 3 * TSM + so) = __ldg((const uint4*)(Blo + gb));
        }
    };

    stage(0, 0);
    __syncthreads();

    const int g = lane >> 2;
    const int q = lane & 3;

    for (int kc = 0; kc < nkc; kc++) {
        if (kc + 1 < nkc) stage(kc + 1, (kc + 1) & 1);
        const __nv_bfloat16* buf = sm + (kc & 1) * 4 * TSM;
        const __nv_bfloat16* sAh = buf + 0 * TSM;
        const __nv_bfloat16* sAl = buf + 1 * TSM;
        const __nv_bfloat16* sBh = buf + 2 * TSM;
        const __nv_bfloat16* sBl = buf + 3 * TSM;
#pragma unroll
        for (int ks = 0; ks < 2; ks++) {
            const int kk = ks * 16 + q * 2;
            uint32_t ah[2][4], al[2][4];
#pragma unroll
            for (int mi = 0; mi < 2; mi++) {
                const int r = wm + mi * 16 + g;
                ah[mi][0] = *(const uint32_t*)(sAh + r * RS + kk);
                ah[mi][1] = *(const uint32_t*)(sAh + (r + 8) * RS + kk);
                ah[mi][2] = *(const uint32_t*)(sAh + r * RS + kk + 8);
                ah[mi][3] = *(const uint32_t*)(sAh + (r + 8) * RS + kk + 8);
                al[mi][0] = *(const uint32_t*)(sAl + r * RS + kk);
                al[mi][1] = *(const uint32_t*)(sAl + (r + 8) * RS + kk);
                al[mi][2] = *(const uint32_t*)(sAl + r * RS + kk + 8);
                al[mi][3] = *(const uint32_t*)(sAl + (r + 8) * RS + kk + 8);
            }
#pragma unroll
            for (int ni = 0; ni < 8; ni++) {
                const int n = wn + ni * 8 + g;
                uint32_t bh[2], bl[2];
                bh[0] = *(const uint32_t*)(sBh + n * RS + kk);
                bh[1] = *(const uint32_t*)(sBh + n * RS + kk + 8);
                bl[0] = *(const uint32_t*)(sBl + n * RS + kk);
                bl[1] = *(const uint32_t*)(sBl + n * RS + kk + 8);
#pragma unroll
                for (int mi = 0; mi < 2; mi++) {
                    MMA16816(acc[mi][ni], ah[mi], bh);
                    MMA16816(acc[mi][ni], ah[mi], bl);
                    MMA16816(acc[mi][ni], al[mi], bh);
                }
            }
        }
        __syncthreads();
    }

#pragma unroll
    for (int mi = 0; mi < 2; mi++) {
        const int row0 = bm + wm + mi * 16 + g;
        float* o0 = out + (size_t)row0 * ldout + bn + wn;
        float* o1 = o0 + (size_t)8 * ldout;
#pragma unroll
        for (int ni = 0; ni < 8; ni++) {
            const int c = ni * 8 + q * 2;
            float2 bb = *(const float2*)&bias[bn + wn + c];
            float2 v0, v1;
            v0.x = acc[mi][ni][0] + bb.x;  v0.y = acc[mi][ni][1] + bb.y;
            v1.x = acc[mi][ni][2] + bb.x;  v1.y = acc[mi][ni][3] + bb.y;
            *(float2*)(o0 + c) = v0;
            *(float2*)(o1 + c) = v1;
        }
    }
}

// ---------------- launch ----------------
extern "C" void kernel_launch(void* const* d_in, const int* in_sizes, int n_in,
                              void* d_out, int out_size)
{
    (void)in_sizes; (void)n_in; (void)out_size;
    const int*   idx   = (const int*)  d_in[0];
    const float* ew    = (const float*)d_in[1];
    const float* Wih0f = (const float*)d_in[2];
    const float* Whh0f = (const float*)d_in[3];
    const float* b0f   = (const float*)d_in[4];
    const float* Wih0b = (const float*)d_in[5];
    const float* Whh0b = (const float*)d_in[6];
    const float* b0b   = (const float*)d_in[7];
    const float* Wih1f = (const float*)d_in[8];
    const float* Whh1f = (const float*)d_in[9];
    const float* b1f   = (const float*)d_in[10];
    const float* Wih1b = (const float*)d_in[11];
    const float* Whh1b = (const float*)d_in[12];
    const float* b1b   = (const float*)d_in[13];
    const float* Wlin  = (const float*)d_in[14];
    const float* blin  = (const float*)d_in[15];
    float* out = (float*)d_out;

    float *x0, *xpf, *xpb, *h0, *h1;
    __nv_bfloat16 *whi, *wlo, *ahi, *alo;
    __nv_bfloat16 *w0fh, *w0fl, *w0bh, *w0bl, *w1fh, *w1fl, *w1bh, *w1bl;
    cudaGetSymbolAddress((void**)&x0,  g_x0);
    cudaGetSymbolAddress((void**)&xpf, g_xpf);
    cudaGetSymbolAddress((void**)&xpb, g_xpb);
    cudaGetSymbolAddress((void**)&h0,  g_h0);
    cudaGetSymbolAddress((void**)&h1,  g_h1);
    cudaGetSymbolAddress((void**)&whi, g_whi);
    cudaGetSymbolAddress((void**)&wlo, g_wlo);
    cudaGetSymbolAddress((void**)&ahi, g_ahi);
    cudaGetSymbolAddress((void**)&alo, g_alo);
    cudaGetSymbolAddress((void**)&w0fh, g_w0fhi);  cudaGetSymbolAddress((void**)&w0fl, g_w0flo);
    cudaGetSymbolAddress((void**)&w0bh, g_w0bhi);  cudaGetSymbolAddress((void**)&w0bl, g_w0blo);
    cudaGetSymbolAddress((void**)&w1fh, g_w1fhi);  cudaGetSymbolAddress((void**)&w1fl, g_w1flo);
    cudaGetSymbolAddress((void**)&w1bh, g_w1bhi);  cudaGetSymbolAddress((void**)&w1bl, g_w1blo);

    const int gemm_smem = 2 * 4 * TSM * (int)sizeof(__nv_bfloat16);   // 81920
    cudaFuncSetAttribute(mma_gemm, cudaFuncAttributeMaxDynamicSharedMemorySize, gemm_smem);

    // 0) embed + canary-fill both h buffers (data-is-flag sync)
    embed_kernel<<<SEQ, 128>>>(idx, ew);
    canary_fill<<<SEQ * 2 * HID / 4 / 256, 256>>>(h0);
    canary_fill<<<SEQ * 2 * HID / 4 / 256, 256>>>(h1);
    // 1) weight/activation splits for layer-0 xproj + head weights
    split_bf16<<<(VOC * KH / 4) / 256, 256>>>(Wlin, whi, wlo);
    split_bf16<<<(SEQ * HID / 4) / 256, 256>>>(x0, ahi, alo);
    split_bf16<<<(G4 * HID / 4) / 256, 256>>>(Wih0f, w0fh, w0fl);
    split_bf16<<<(G4 * HID / 4) / 256, 256>>>(Wih0b, w0bh, w0bl);
    // 2) layer-0 xproj (M=SEQ, N=G4, K=HID)
    {
        dim3 grid(SEQ / 128, G4 / 128);      // 32 x 16
        mma_gemm<<<grid, 256, gemm_smem>>>(ahi, alo, w0fh, w0fl, b0f, xpf, HID, G4);
        mma_gemm<<<grid, 256, gemm_smem>>>(ahi, alo, w0bh, w0bl, b0b, xpb, HID, G4);
    }
    // 3) layer-0 recurrence
    lstm_layer_kernel<<<2 * NCD, NTH>>>(xpf, xpb, Whh0f, Whh0b, h0);
    // 4) splits for layer-1 xproj
    split_bf16<<<(SEQ * KH / 4) / 256, 256>>>(h0, ahi, alo);
    split_bf16<<<(G4 * KH / 4) / 256, 256>>>(Wih1f, w1fh, w1fl);
    split_bf16<<<(G4 * KH / 4) / 256, 256>>>(Wih1b, w1bh, w1bl);
    // 5) layer-1 xproj (K=KH)
    {
        dim3 grid(SEQ / 128, G4 / 128);
        mma_gemm<<<grid, 256, gemm_smem>>>(ahi, alo, w1fh, w1fl, b1f, xpf, KH, G4);
        mma_gemm<<<grid, 256, gemm_smem>>>(ahi, alo, w1bh, w1bl, b1b, xpb, KH, G4);
    }
    // 6) layer-1 recurrence
    lstm_layer_kernel<<<2 * NCD, NTH>>>(xpf, xpb, Whh1f, Whh1b, h1);
    // 7) head
    split_bf16<<<(SEQ * KH / 4) / 256, 256>>>(h1, ahi, alo);
    {
        dim3 grid(SEQ / 128, VOC / 128);     // 32 x 250
        mma_gemm<<<grid, 256, gemm_smem>>>(ahi, alo, whi, wlo, blin, out, KH, VOC);
    }
}

// round 14
// speedup vs baseline: 2.1464x; 1.0624x over previous
#include <cuda_runtime.h>
#include <cuda_bf16.h>
#include <cstdint>

#define SEQ    4096
#define HID    512
#define G4     2048          // 4*HID
#define NCD    32            // CTAs per direction in the recurrence
#define NTH    512           // threads per LSTM CTA
#define JH     16            // h outputs per CTA (64 gate rows)
#define VOC    32000
#define KH     1024          // head GEMM K (2*HID)

// ---------------- scratch (device globals; no allocation allowed) ----------------
static __device__ __align__(16) float    g_x0 [SEQ * HID];
static __device__ __align__(16) float    g_xpf[SEQ * G4];
static __device__ __align__(16) float    g_xpb[SEQ * G4];
static __device__ __align__(16) float    g_h0 [SEQ * 2 * HID];
static __device__ __align__(16) float    g_h1 [SEQ * 2 * HID];
// bf16 hi/lo splits
static __device__ __align__(16) __nv_bfloat16 g_whi [VOC * KH];
static __device__ __align__(16) __nv_bfloat16 g_wlo [VOC * KH];
static __device__ __align__(16) __nv_bfloat16 g_ahi [SEQ * KH];
static __device__ __align__(16) __nv_bfloat16 g_alo [SEQ * KH];
static __device__ __align__(16) __nv_bfloat16 g_w0fhi[G4 * HID], g_w0flo[G4 * HID];
static __device__ __align__(16) __nv_bfloat16 g_w0bhi[G4 * HID], g_w0blo[G4 * HID];
static __device__ __align__(16) __nv_bfloat16 g_w1fhi[G4 * KH],  g_w1flo[G4 * KH];
static __device__ __align__(16) __nv_bfloat16 g_w1bhi[G4 * KH],  g_w1blo[G4 * KH];

// ---------------- embed ----------------
__global__ void embed_kernel(const int* __restrict__ idx, const float* __restrict__ ew) {
    int s = blockIdx.x;
    int r = idx[s];
    ((float4*)(g_x0 + (size_t)s * HID))[threadIdx.x] =
        ((const float4*)(ew + (size_t)r * HID))[threadIdx.x];
}

// ---------------- canary fill (NaN) for the data-is-flag h exchange ----------------
__global__ void canary_fill(float* __restrict__ p) {
    const unsigned NANP = 0x7FC00000u;
    uint4 v = make_uint4(NANP, NANP, NANP, NANP);
    ((uint4*)p)[(size_t)blockIdx.x * 256 + threadIdx.x] = v;
}

// ---------------- fp32 -> bf16 hi/lo split ----------------
__global__ void split_bf16(const float* __restrict__ src,
                           __nv_bfloat16* __restrict__ hi, __nv_bfloat16* __restrict__ lo) {
    int i = blockIdx.x * 256 + threadIdx.x;        // one float4 per thread
    float4 v = __ldg((const float4*)src + i);
    __nv_bfloat16 h0 = __float2bfloat16_rn(v.x), h1 = __float2bfloat16_rn(v.y);
    __nv_bfloat16 h2 = __float2bfloat16_rn(v.z), h3 = __float2bfloat16_rn(v.w);
    __nv_bfloat16 l0 = __float2bfloat16_rn(v.x - __bfloat162float(h0));
    __nv_bfloat16 l1 = __float2bfloat16_rn(v.y - __bfloat162float(h1));
    __nv_bfloat16 l2 = __float2bfloat16_rn(v.z - __bfloat162float(h2));
    __nv_bfloat16 l3 = __float2bfloat16_rn(v.w - __bfloat162float(h3));
    ushort4 hv = make_ushort4(*(unsigned short*)&h0, *(unsigned short*)&h1,
                              *(unsigned short*)&h2, *(unsigned short*)&h3);
    ushort4 lv = make_ushort4(*(unsigned short*)&l0, *(unsigned short*)&l1,
                              *(unsigned short*)&l2, *(unsigned short*)&l3);
    ((ushort4*)hi)[i] = hv;
    ((ushort4*)lo)[i] = lv;
}

// ---------------- persistent bidirectional LSTM layer ----------------
// R11 structure (CTA-barrier-coupled NaN-canary data-is-flag poll — the only
// weak-poll form proven live on this part) + parallel gate epilogue:
// 64 threads compute the 64 gate activations concurrently instead of 16
// threads running ~6 serial MUFU chains each.
__device__ __forceinline__ float4 ldcg_f4(const float4* p) {
    float4 v;
    asm volatile("ld.global.cg.v4.f32 {%0,%1,%2,%3}, [%4];"
                 : "=f"(v.x), "=f"(v.y), "=f"(v.z), "=f"(v.w) : "l"(p) : "memory");
    return v;
}

__global__ void __launch_bounds__(NTH, 1) lstm_layer_kernel(
    const float* __restrict__ xpf, const float* __restrict__ xpb,
    const float* __restrict__ Whf, const float* __restrict__ Whb,
    float* __restrict__ hcat)
{
    __shared__ __align__(16) float hsh[HID];
    __shared__ float xps[4 * JH];          // 64
    __shared__ float pre[4 * JH];          // 64
    __shared__ float gact[4 * JH];         // 64 parallel gate activations
    __shared__ float csh[JH];

    const int tid = threadIdx.x;
    const int dir = blockIdx.x >> 5;
    const int cid = blockIdx.x & 31;
    const float* xp = dir ? xpb : xpf;
    const float* W  = dir ? Whb : Whf;

    const int rp   = tid >> 4;
    const int ks   = tid & 15;
    const int row0 = rp * 2, row1 = rp * 2 + 1;

    float w0r[32], w1r[32];
    {
        const int g0 = row0 >> 4, j0 = row0 & 15;
        const int g1 = row1 >> 4, j1 = row1 & 15;
        const size_t gr0 = (size_t)(g0 * HID + cid * JH + j0) * HID;
        const size_t gr1 = (size_t)(g1 * HID + cid * JH + j1) * HID;
#pragma unroll
        for (int m = 0; m < 8; m++) {
            const int k = ks * 4 + m * 64;
            float4 v0 = __ldg((const float4*)&W[gr0 + k]);
            float4 v1 = __ldg((const float4*)&W[gr1 + k]);
            w0r[4 * m + 0] = v0.x;  w0r[4 * m + 1] = v0.y;
            w0r[4 * m + 2] = v0.z;  w0r[4 * m + 3] = v0.w;
            w1r[4 * m + 0] = v1.x;  w1r[4 * m + 1] = v1.y;
            w1r[4 * m + 2] = v1.z;  w1r[4 * m + 3] = v1.w;
        }
    }
    if (tid < 128) ((float4*)hsh)[tid] = make_float4(0.f, 0.f, 0.f, 0.f);
    if (tid < JH) csh[tid] = 0.f;
    __syncthreads();

    for (int t = 0; t < SEQ; t++) {
        const int tt = dir ? (SEQ - 1 - t) : t;
        // prefetch this step's xproj values (immutable; includes bias)
        float xval = 0.f;
        if (tid < 4 * JH) {
            int g = tid >> 4, j = tid & 15;
            xval = __ldg(&xp[(size_t)tt * G4 + g * HID + cid * JH + j]);
        }
        if (t > 0) {
            const int ttp = dir ? (tt + 1) : (tt - 1);
            const float4* hrow = (const float4*)&hcat[(size_t)ttp * (2 * HID) + dir * HID];
            float4 h4 = make_float4(0.f, 0.f, 0.f, 0.f);
            for (;;) {
                bool ok = true;
                if (tid < 128) {
                    h4 = ldcg_f4(hrow + tid);
                    // canary is NaN; real h is always finite
                    ok = (h4.x == h4.x) && (h4.y == h4.y) && (h4.z == h4.z) && (h4.w == h4.w);
                }
                if (__syncthreads_and(ok)) break;
            }
            if (tid < 128) ((float4*)hsh)[tid] = h4;
            __syncthreads();
        }
        // matvec: pre[r] = sum_k h[k] * Whh[r][k], 2 rows per thread, strided k
        float a0 = 0.f, a1 = 0.f;
#pragma unroll
        for (int m = 0; m < 8; m++) {
            int k = ks * 4 + m * 64;
            float4 h4 = *(const float4*)&hsh[k];
            a0 += h4.x * w0r[4 * m] + h4.y * w0r[4 * m + 1]
                + h4.z * w0r[4 * m + 2] + h4.w * w0r[4 * m + 3];
            a1 += h4.x * w1r[4 * m] + h4.y * w1r[4 * m + 1]
                + h4.z * w1r[4 * m + 2] + h4.w * w1r[4 * m + 3];
        }
#pragma unroll
        for (int off = 8; off > 0; off >>= 1) {
            a0 += __shfl_down_sync(0xffffffffu, a0, off, 16);
            a1 += __shfl_down_sync(0xffffffffu, a1, off, 16);
        }
        if (ks == 0) { pre[row0] = a0; pre[row1] = a1; }
        if (tid < 4 * JH) xps[tid] = xval;
        __syncthreads();

        // parallel gate activations: one thread per gate row (64 total)
        if (tid < 4 * JH) {
            float z = xps[tid] + pre[tid];
            gact[tid] = ((tid >> 4) == 2)
                      ? (2.f / (1.f + __expf(-2.f * z)) - 1.f)   // g gate: tanh
                      : (1.f / (1.f + __expf(-z)));               // i,f,o: sigmoid
        }
        __syncthreads();

        if (tid < JH) {
            const int j = tid;
            float ig = gact[j];
            float fg = gact[JH + j];
            float gg = gact[2 * JH + j];
            float og = gact[3 * JH + j];
            float c  = fg * csh[j] + ig * gg;
            csh[j] = c;
            float h = og * (2.f / (1.f + __expf(-2.f * c)) - 1.f);
            const int hj = cid * JH + j;
            __stcg(&hcat[(size_t)tt * (2 * HID) + dir * HID + hj], h);  // data IS the flag
        }
        __syncthreads();
    }
}

// ---------------- bf16 mma.sync GEMM: out[M,N] = A[M,K]*B[N,K]^T + bias ----------
#define KC    32
#define RS    40                 // padded SMEM row stride (bf16 elems)
#define TSM   (128 * RS)         // bf16 elems per tile

#define MMA16816(c, a, b) \
    asm volatile("mma.sync.aligned.m16n8k16.row.col.f32.bf16.bf16.f32 " \
        "{%0,%1,%2,%3}, {%4,%5,%6,%7}, {%8,%9}, {%0,%1,%2,%3};" \
        : "+f"((c)[0]), "+f"((c)[1]), "+f"((c)[2]), "+f"((c)[3]) \
        : "r"((a)[0]), "r"((a)[1]), "r"((a)[2]), "r"((a)[3]), \
          "r"((b)[0]), "r"((b)[1]))

__global__ void __launch_bounds__(256, 1) mma_gemm(
    const __nv_bfloat16* __restrict__ Ahi, const __nv_bfloat16* __restrict__ Alo,
    const __nv_bfloat16* __restrict__ Bhi, const __nv_bfloat16* __restrict__ Blo,
    const float* __restrict__ bias, float* __restrict__ out,
    int K, int ldout)
{
    extern __shared__ __nv_bfloat16 sm[];   // [2][4][TSM]: Ahi, Alo, Bhi, Blo
    const int tid  = threadIdx.x;
    const int wid  = tid >> 5;
    const int lane = tid & 31;
    const int wm   = (wid >> 1) * 32;
    const int wn   = (wid & 1) * 64;
    const int bm   = blockIdx.x * 128;      // m fastest -> B streams once per wave
    const int bn   = blockIdx.y * 128;
    const int nkc  = K / KC;

    float acc[2][8][4];
#pragma unroll
    for (int i = 0; i < 2; i++)
#pragma unroll
        for (int j = 0; j < 8; j++)
#pragma unroll
            for (int q = 0; q < 4; q++) acc[i][j][q] = 0.f;

    auto stage = [&](int kc, int buf) {
        const int k0 = kc * KC;
        __nv_bfloat16* b = sm + buf * 4 * TSM;
#pragma unroll
        for (int it = 0; it < 2; it++) {
            int idx = tid + it * 256;        // 0..511
            int row = idx >> 2;              // 0..127
            int c4  = idx & 3;
            size_t ga = (size_t)(bm + row) * K + k0 + c4 * 8;
            size_t gb = (size_t)(bn + row) * K + k0 + c4 * 8;
            uint32_t so = row * RS + c4 * 8;
            *(uint4*)(b + 0 * TSM + so) = __ldg((const uint4*)(Ahi + ga));
            *(uint4*)(b + 1 * TSM + so) = __ldg((const uint4*)(Alo + ga));
            *(uint4*)(b + 2 * TSM + so) = __ldg((const uint4*)(Bhi + gb));
            *(uint4*)(b + 3 * TSM + so) = __ldg((const uint4*)(Blo + gb));
        }
    };

    stage(0, 0);
    __syncthreads();

    const int g = lane >> 2;
    const int q = lane & 3;

    for (int kc = 0; kc < nkc; kc++) {
        if (kc + 1 < nkc) stage(kc + 1, (kc + 1) & 1);
        const __nv_bfloat16* buf = sm + (kc & 1) * 4 * TSM;
        const __nv_bfloat16* sAh = buf + 0 * TSM;
        const __nv_bfloat16* sAl = buf + 1 * TSM;
        const __nv_bfloat16* sBh = buf + 2 * TSM;
        const __nv_bfloat16* sBl = buf + 3 * TSM;
#pragma unroll
        for (int ks = 0; ks < 2; ks++) {
            const int kk = ks * 16 + q * 2;
            uint32_t ah[2][4], al[2][4];
#pragma unroll
            for (int mi = 0; mi < 2; mi++) {
                const int r = wm + mi * 16 + g;
                ah[mi][0] = *(const uint32_t*)(sAh + r * RS + kk);
                ah[mi][1] = *(const uint32_t*)(sAh + (r + 8) * RS + kk);
                ah[mi][2] = *(const uint32_t*)(sAh + r * RS + kk + 8);
                ah[mi][3] = *(const uint32_t*)(sAh + (r + 8) * RS + kk + 8);
                al[mi][0] = *(const uint32_t*)(sAl + r * RS + kk);
                al[mi][1] = *(const uint32_t*)(sAl + (r + 8) * RS + kk);
                al[mi][2] = *(const uint32_t*)(sAl + r * RS + kk + 8);
                al[mi][3] = *(const uint32_t*)(sAl + (r + 8) * RS + kk + 8);
            }
#pragma unroll
            for (int ni = 0; ni < 8; ni++) {
                const int n = wn + ni * 8 + g;
                uint32_t bh[2], bl[2];
                bh[0] = *(const uint32_t*)(sBh + n * RS + kk);
                bh[1] = *(const uint32_t*)(sBh + n * RS + kk + 8);
                bl[0] = *(const uint32_t*)(sBl + n * RS + kk);
                bl[1] = *(const uint32_t*)(sBl + n * RS + kk + 8);
#pragma unroll
                for (int mi = 0; mi < 2; mi++) {
                    MMA16816(acc[mi][ni], ah[mi], bh);
                    MMA16816(acc[mi][ni], ah[mi], bl);
                    MMA16816(acc[mi][ni], al[mi], bh);
                }
            }
        }
        __syncthreads();
    }

#pragma unroll
    for (int mi = 0; mi < 2; mi++) {
        const int row0 = bm + wm + mi * 16 + g;
        float* o0 = out + (size_t)row0 * ldout + bn + wn;
        float* o1 = o0 + (size_t)8 * ldout;
#pragma unroll
        for (int ni = 0; ni < 8; ni++) {
            const int c = ni * 8 + q * 2;
            float2 bb = *(const float2*)&bias[bn + wn + c];
            float2 v0, v1;
            v0.x = acc[mi][ni][0] + bb.x;  v0.y = acc[mi][ni][1] + bb.y;
            v1.x = acc[mi][ni][2] + bb.x;  v1.y = acc[mi][ni][3] + bb.y;
            *(float2*)(o0 + c) = v0;
            *(float2*)(o1 + c) = v1;
        }
    }
}

// ---------------- launch ----------------
extern "C" void kernel_launch(void* const* d_in, const int* in_sizes, int n_in,
                              void* d_out, int out_size)
{
    (void)in_sizes; (void)n_in; (void)out_size;
    const int*   idx   = (const int*)  d_in[0];
    const float* ew    = (const float*)d_in[1];
    const float* Wih0f = (const float*)d_in[2];
    const float* Whh0f = (const float*)d_in[3];
    const float* b0f   = (const float*)d_in[4];
    const float* Wih0b = (const float*)d_in[5];
    const float* Whh0b = (const float*)d_in[6];
    const float* b0b   = (const float*)d_in[7];
    const float* Wih1f = (const float*)d_in[8];
    const float* Whh1f = (const float*)d_in[9];
    const float* b1f   = (const float*)d_in[10];
    const float* Wih1b = (const float*)d_in[11];
    const float* Whh1b = (const float*)d_in[12];
    const float* b1b   = (const float*)d_in[13];
    const float* Wlin  = (const float*)d_in[14];
    const float* blin  = (const float*)d_in[15];
    float* out = (float*)d_out;

    float *x0, *xpf, *xpb, *h0, *h1;
    __nv_bfloat16 *whi, *wlo, *ahi, *alo;
    __nv_bfloat16 *w0fh, *w0fl, *w0bh, *w0bl, *w1fh, *w1fl, *w1bh, *w1bl;
    cudaGetSymbolAddress((void**)&x0,  g_x0);
    cudaGetSymbolAddress((void**)&xpf, g_xpf);
    cudaGetSymbolAddress((void**)&xpb, g_xpb);
    cudaGetSymbolAddress((void**)&h0,  g_h0);
    cudaGetSymbolAddress((void**)&h1,  g_h1);
    cudaGetSymbolAddress((void**)&whi, g_whi);
    cudaGetSymbolAddress((void**)&wlo, g_wlo);
    cudaGetSymbolAddress((void**)&ahi, g_ahi);
    cudaGetSymbolAddress((void**)&alo, g_alo);
    cudaGetSymbolAddress((void**)&w0fh, g_w0fhi);  cudaGetSymbolAddress((void**)&w0fl, g_w0flo);
    cudaGetSymbolAddress((void**)&w0bh, g_w0bhi);  cudaGetSymbolAddress((void**)&w0bl, g_w0blo);
    cudaGetSymbolAddress((void**)&w1fh, g_w1fhi);  cudaGetSymbolAddress((void**)&w1fl, g_w1flo);
    cudaGetSymbolAddress((void**)&w1bh, g_w1bhi);  cudaGetSymbolAddress((void**)&w1bl, g_w1blo);

    const int gemm_smem = 2 * 4 * TSM * (int)sizeof(__nv_bfloat16);   // 81920
    cudaFuncSetAttribute(mma_gemm, cudaFuncAttributeMaxDynamicSharedMemorySize, gemm_smem);

    // 0) embed + canary-fill both h buffers (data-is-flag sync)
    embed_kernel<<<SEQ, 128>>>(idx, ew);
    canary_fill<<<SEQ * 2 * HID / 4 / 256, 256>>>(h0);
    canary_fill<<<SEQ * 2 * HID / 4 / 256, 256>>>(h1);
    // 1) weight/activation splits for layer-0 xproj + head weights
    split_bf16<<<(VOC * KH / 4) / 256, 256>>>(Wlin, whi, wlo);
    split_bf16<<<(SEQ * HID / 4) / 256, 256>>>(x0, ahi, alo);
    split_bf16<<<(G4 * HID / 4) / 256, 256>>>(Wih0f, w0fh, w0fl);
    split_bf16<<<(G4 * HID / 4) / 256, 256>>>(Wih0b, w0bh, w0bl);
    // 2) layer-0 xproj (M=SEQ, N=G4, K=HID)
    {
        dim3 grid(SEQ / 128, G4 / 128);      // 32 x 16
        mma_gemm<<<grid, 256, gemm_smem>>>(ahi, alo, w0fh, w0fl, b0f, xpf, HID, G4);
        mma_gemm<<<grid, 256, gemm_smem>>>(ahi, alo, w0bh, w0bl, b0b, xpb, HID, G4);
    }
    // 3) layer-0 recurrence
    lstm_layer_kernel<<<2 * NCD, NTH>>>(xpf, xpb, Whh0f, Whh0b, h0);
    // 4) splits for layer-1 xproj
    split_bf16<<<(SEQ * KH / 4) / 256, 256>>>(h0, ahi, alo);
    split_bf16<<<(G4 * KH / 4) / 256, 256>>>(Wih1f, w1fh, w1fl);
    split_bf16<<<(G4 * KH / 4) / 256, 256>>>(Wih1b, w1bh, w1bl);
    // 5) layer-1 xproj (K=KH)
    {
        dim3 grid(SEQ / 128, G4 / 128);
        mma_gemm<<<grid, 256, gemm_smem>>>(ahi, alo, w1fh, w1fl, b1f, xpf, KH, G4);
        mma_gemm<<<grid, 256, gemm_smem>>>(ahi, alo, w1bh, w1bl, b1b, xpb, KH, G4);
    }
    // 6) layer-1 recurrence
    lstm_layer_kernel<<<2 * NCD, NTH>>>(xpf, xpb, Whh1f, Whh1b, h1);
    // 7) head
    split_bf16<<<(SEQ * KH / 4) / 256, 256>>>(h1, ahi, alo);
    {
        dim3 grid(SEQ / 128, VOC / 128);     // 32 x 250
        mma_gemm<<<grid, 256, gemm_smem>>>(ahi, alo, whi, wlo, blin, out, KH, VOC);
    }
}